// round 10
// baseline (speedup 1.0000x reference)
#include <cuda_runtime.h>
#include <cuda_bf16.h>
#include <math.h>
#include <stdint.h>

// Problem constants
#define BB 2
#define SS 2048
#define DM 1024
#define HH 16
#define HD 64
#define DF 4096
#define NTOK (BB * SS)          // 4096
#define NEGV (-1e9f)
#define EPS 1e-6f

// ---------------------------------------------------------------------------
// Scratch (device globals — no allocation allowed)
// ---------------------------------------------------------------------------
__device__ float g_n1[NTOK * DM];
__device__ float g_qkv[(long)NTOK * 3 * DM];   // q|k|v interleaved per row
__device__ float g_wcat[DM * 3 * DM];          // Wq|Wk|Wv  [1024][3072]
__device__ float g_bcat[3 * DM];
__device__ float g_attn[NTOK * DM];
__device__ float g_h[NTOK * DM];
__device__ float g_n2[NTOK * DM];
__device__ float g_ffn[(long)NTOK * DF];

// ---------------------------------------------------------------------------
// Helpers
// ---------------------------------------------------------------------------
__device__ __forceinline__ uint32_t f2tf(float f) {
    uint32_t u;
    asm("cvt.rna.tf32.f32 %0, %1;" : "=r"(u) : "f"(f));
    return u;
}
__device__ __forceinline__ uint4 cvt4(float4 v) {
    uint4 r;
    r.x = f2tf(v.x); r.y = f2tf(v.y); r.z = f2tf(v.z); r.w = f2tf(v.w);
    return r;
}
// pair-permute two 4-chunks (cols k..k+3, k+4..k+7) into (k,k+4)(k+1,k+5)...
__device__ __forceinline__ void perm8(float4 c0, float4 c1, uint4& o0, uint4& o1) {
    o0 = make_uint4(f2tf(c0.x), f2tf(c1.x), f2tf(c0.y), f2tf(c1.y));
    o1 = make_uint4(f2tf(c0.z), f2tf(c1.z), f2tf(c0.w), f2tf(c1.w));
}
__device__ __forceinline__ void mma_tf32(float c[4], uint32_t a0, uint32_t a1,
                                         uint32_t a2, uint32_t a3,
                                         uint32_t b0, uint32_t b1) {
    asm volatile(
        "mma.sync.aligned.m16n8k8.row.col.f32.tf32.tf32.f32 "
        "{%0,%1,%2,%3}, {%4,%5,%6,%7}, {%8,%9}, {%0,%1,%2,%3};"
        : "+f"(c[0]), "+f"(c[1]), "+f"(c[2]), "+f"(c[3])
        : "r"(a0), "r"(a1), "r"(a2), "r"(a3), "r"(b0), "r"(b1));
}
__device__ __forceinline__ void cpa16(void* dst, const void* src) {
    uint32_t d = (uint32_t)__cvta_generic_to_shared(dst);
    asm volatile("cp.async.cg.shared.global [%0], [%1], 16;" :: "r"(d), "l"(src));
}
__device__ __forceinline__ void cpa_commit() {
    asm volatile("cp.async.commit_group;" ::: "memory");
}
__device__ __forceinline__ void cpa_wait0() {
    asm volatile("cp.async.wait_group 0;" ::: "memory");
}

// ---------------------------------------------------------------------------
// Concat Wq|Wk|Wv and biases into contiguous [1024][3072] / [3072]
// ---------------------------------------------------------------------------
__global__ __launch_bounds__(256) void concat_w(
    const float* __restrict__ Wq, const float* __restrict__ Wk,
    const float* __restrict__ Wv, const float* __restrict__ bq,
    const float* __restrict__ bk, const float* __restrict__ bv,
    float* __restrict__ wcat, float* __restrict__ bcat) {
    long i = blockIdx.x * 256L + threadIdx.x;
    int row = (int)(i / (3 * DM));
    int col = (int)(i % (3 * DM));
    const float* W = (col < DM) ? Wq : ((col < 2 * DM) ? Wk : Wv);
    wcat[i] = W[row * DM + (col & (DM - 1))];
    if (i < 3 * DM) {
        const float* bb = (i < DM) ? bq : ((i < 2 * DM) ? bk : bv);
        bcat[i] = bb[i & (DM - 1)];
    }
}

// ---------------------------------------------------------------------------
// LayerNorm (torch semantics: unbiased std (ddof=1), eps added to std)
// ---------------------------------------------------------------------------
__global__ __launch_bounds__(256) void ln_kernel(const float* __restrict__ x,
                                                 const float* __restrict__ alpha,
                                                 const float* __restrict__ beta,
                                                 float* __restrict__ out) {
    long row = blockIdx.x;
    const float4* xr = (const float4*)(x + row * DM);
    float4 v = xr[threadIdx.x];

    float s  = v.x + v.y + v.z + v.w;
    float ss = v.x * v.x + v.y * v.y + v.z * v.z + v.w * v.w;

    __shared__ float sa[8], sb[8];
#pragma unroll
    for (int o = 16; o > 0; o >>= 1) {
        s  += __shfl_xor_sync(0xffffffffu, s, o);
        ss += __shfl_xor_sync(0xffffffffu, ss, o);
    }
    if ((threadIdx.x & 31) == 0) { sa[threadIdx.x >> 5] = s; sb[threadIdx.x >> 5] = ss; }
    __syncthreads();
    s = 0.f; ss = 0.f;
#pragma unroll
    for (int i = 0; i < 8; i++) { s += sa[i]; ss += sb[i]; }

    float mean = s * (1.0f / DM);
    float var  = (ss - (float)DM * mean * mean) * (1.0f / (DM - 1));
    var = fmaxf(var, 0.0f);
    float inv  = alpha[0] / (sqrtf(var) + EPS);
    float bta  = beta[0];

    float4 o;
    o.x = (v.x - mean) * inv + bta;
    o.y = (v.y - mean) * inv + bta;
    o.z = (v.z - mean) * inv + bta;
    o.w = (v.w - mean) * inv + bta;
    ((float4*)(out + row * DM))[threadIdx.x] = o;
}

// ---------------------------------------------------------------------------
// Flash attention v3: cp.async double-buffered K/V; conversion pass pair-
// permutes K (in-place, per-row-group ownership) so S-phase K fragments are
// LDS.64.  V identity-converted in place (frags stay LDS.32).  P private.
// K/V strides 72 (bank 8g+2tg / 8tg+g patterns, conflict-free).
// ---------------------------------------------------------------------------
#define KST 4608
#define VST 4608
#define F_KOFF 0
#define F_VOFF (2 * KST)
#define F_POFF (2 * KST + 2 * VST)
#define F_MOFF (F_POFF + 4608)
#define F_AOFF (F_MOFF + 128)
#define F_SMEM ((F_AOFF + 128) * 4)   // 93,184 B

__global__ __launch_bounds__(256, 2) void flash_kernel(
    const float* __restrict__ qkv, const int* __restrict__ mask,
    float* __restrict__ out) {
    constexpr int LDQ = 3 * DM;
    constexpr int KS = 72;
    constexpr int VS = 72;
    extern __shared__ float fsm[];
    float* Kst = fsm + F_KOFF;
    float* Vst = fsm + F_VOFF;
    uint32_t* Pst = (uint32_t*)(fsm + F_POFF);
    int* Mst = (int*)(fsm + F_MOFF);
    float* mAddF = fsm + F_AOFF;

    int qb = blockIdx.x * 128;
    int h  = blockIdx.y;
    int b  = blockIdx.z;
    const float* qp = qkv + (long)b * SS * LDQ + h * HD;
    const float* kp = qp + DM;
    const float* vp = qp + 2 * DM;
    const int* mp = mask + b * SS;

    int tid = threadIdx.x, warp = tid >> 5, lane = tid & 31;
    int g = lane >> 2, tg = lane & 3;
    int rrow = qb + warp * 16 + g;
    const int lr = tid >> 4;            // 0..15 loader row base
    const int lc = (tid & 15) * 4;      // 0..60 loader col

    // Q fragments straight from gmem (scaled by 1/sqrt(HD)=0.125, tf32)
    uint32_t qf[8][4];
#pragma unroll
    for (int ks = 0; ks < 8; ks++) {
        int c0 = ks * 8 + tg;
        qf[ks][0] = f2tf(0.125f * qp[(long)rrow * LDQ + c0]);
        qf[ks][1] = f2tf(0.125f * qp[(long)(rrow + 8) * LDQ + c0]);
        qf[ks][2] = f2tf(0.125f * qp[(long)rrow * LDQ + c0 + 4]);
        qf[ks][3] = f2tf(0.125f * qp[(long)(rrow + 8) * LDQ + c0 + 4]);
    }

    uint32_t* Psw = Pst + warp * 576;   // warp-private 16x36

    float m0 = -INFINITY, m1 = -INFINITY, l0 = 0.f, l1 = 0.f;
    float oacc[8][4];
#pragma unroll
    for (int nf = 0; nf < 8; nf++)
#pragma unroll
        for (int c = 0; c < 4; c++) oacc[nf][c] = 0.f;

    auto issue = [&](int t, int s) {
        int k0 = t * 64;
#pragma unroll
        for (int i = 0; i < 4; i++) {
            int row = lr + 16 * i;
            cpa16(Kst + s * KST + row * KS + lc, kp + (long)(k0 + row) * LDQ + lc);
            cpa16(Vst + s * VST + row * VS + lc, vp + (long)(k0 + row) * LDQ + lc);
        }
        if (tid < 16) cpa16(&Mst[s * 64 + tid * 4], &mp[k0 + tid * 4]);
        cpa_commit();
    };

    issue(0, 0);

    for (int t = 0; t < SS / 64; t++) {
        int s = t & 1;
        cpa_wait0();
        __syncthreads();

        if (t + 1 < SS / 64) issue(t + 1, s ^ 1);

        // conversion pass: K pair-permuted in place, V identity in place
        {
            float* Kp = Kst + s * KST;
            int krow = tid & 63;
            int kg0 = tid >> 6;          // 0..3
#pragma unroll
            for (int gi = 0; gi < 2; gi++) {
                int G = kg0 + 4 * gi;
                float4 c0 = *(float4*)(Kp + krow * KS + 8 * G);
                float4 c1 = *(float4*)(Kp + krow * KS + 8 * G + 4);
                uint4 o0, o1;
                perm8(c0, c1, o0, o1);
                *(uint4*)(Kp + krow * KS + 8 * G) = o0;
                *(uint4*)(Kp + krow * KS + 8 * G + 4) = o1;
            }
            float* Vp = Vst + s * VST;
#pragma unroll
            for (int i = 0; i < 4; i++) {
                int row = lr + 16 * i;
                float4 v4 = *(float4*)(Vp + row * VS + lc);
                *(uint4*)(Vp + row * VS + lc) = cvt4(v4);
            }
            if (tid < 64) mAddF[s * 64 + tid] = (Mst[s * 64 + tid] == 0) ? NEGV : 0.f;
        }
        __syncthreads();

        const uint32_t* Ku = (const uint32_t*)(Kst + s * KST);
        const uint32_t* Vu = (const uint32_t*)(Vst + s * VST);
        const float* mA = mAddF + s * 64;

        // S = (Q/8) @ K^T : 16x64 per warp; K frags via LDS.64 (pair layout)
        float sacc[8][4];
#pragma unroll
        for (int nf = 0; nf < 8; nf++)
#pragma unroll
            for (int c = 0; c < 4; c++) sacc[nf][c] = 0.f;
#pragma unroll
        for (int ks = 0; ks < 8; ks++) {
#pragma unroll
            for (int nf = 0; nf < 8; nf++) {
                int c = nf * 8 + g;
                uint2 kb = *(const uint2*)&Ku[c * KS + ks * 8 + 2 * tg];
                mma_tf32(sacc[nf], qf[ks][0], qf[ks][1], qf[ks][2], qf[ks][3],
                         kb.x, kb.y);
            }
        }

        // mask + tile rowmax
        float tm0 = -INFINITY, tm1 = -INFINITY;
#pragma unroll
        for (int nf = 0; nf < 8; nf++) {
            float2 ma = *(const float2*)&mA[nf * 8 + 2 * tg];
            sacc[nf][0] += ma.x; sacc[nf][1] += ma.y;
            sacc[nf][2] += ma.x; sacc[nf][3] += ma.y;
            tm0 = fmaxf(tm0, fmaxf(sacc[nf][0], sacc[nf][1]));
            tm1 = fmaxf(tm1, fmaxf(sacc[nf][2], sacc[nf][3]));
        }
#pragma unroll
        for (int o = 1; o <= 2; o <<= 1) {
            tm0 = fmaxf(tm0, __shfl_xor_sync(0xffffffffu, tm0, o));
            tm1 = fmaxf(tm1, __shfl_xor_sync(0xffffffffu, tm1, o));
        }
        float nm0 = fmaxf(m0, tm0), nm1 = fmaxf(m1, tm1);
        float r0 = __expf(m0 - nm0), r1 = __expf(m1 - nm1);

        float s0 = 0.f, s1 = 0.f;
#pragma unroll
        for (int nf = 0; nf < 8; nf++) {
            sacc[nf][0] = __expf(sacc[nf][0] - nm0);
            sacc[nf][1] = __expf(sacc[nf][1] - nm0);
            sacc[nf][2] = __expf(sacc[nf][2] - nm1);
            sacc[nf][3] = __expf(sacc[nf][3] - nm1);
            s0 += sacc[nf][0] + sacc[nf][1];
            s1 += sacc[nf][2] + sacc[nf][3];
        }
#pragma unroll
        for (int o = 1; o <= 2; o <<= 1) {
            s0 += __shfl_xor_sync(0xffffffffu, s0, o);
            s1 += __shfl_xor_sync(0xffffffffu, s1, o);
        }
        l0 = l0 * r0 + s0; l1 = l1 * r1 + s1;
        m0 = nm0; m1 = nm1;
#pragma unroll
        for (int nf = 0; nf < 8; nf++) {
            oacc[nf][0] *= r0; oacc[nf][1] *= r0;
            oacc[nf][2] *= r1; oacc[nf][3] *= r1;
        }

        // O += P @ V in two 32-key halves (P chunk 16x32, stride 36, private)
#pragma unroll
        for (int half = 0; half < 2; half++) {
            __syncwarp();
#pragma unroll
            for (int nf4 = 0; nf4 < 4; nf4++) {
                int nf = half * 4 + nf4;
                *(uint2*)&Psw[g * 36 + nf4 * 8 + 2 * tg] =
                    make_uint2(f2tf(sacc[nf][0]), f2tf(sacc[nf][1]));
                *(uint2*)&Psw[(g + 8) * 36 + nf4 * 8 + 2 * tg] =
                    make_uint2(f2tf(sacc[nf][2]), f2tf(sacc[nf][3]));
            }
            __syncwarp();
#pragma unroll
            for (int ks4 = 0; ks4 < 4; ks4++) {
                int ks = half * 4 + ks4;
                uint32_t a0 = Psw[g * 36 + ks4 * 8 + tg];
                uint32_t a1 = Psw[(g + 8) * 36 + ks4 * 8 + tg];
                uint32_t a2 = Psw[g * 36 + ks4 * 8 + tg + 4];
                uint32_t a3 = Psw[(g + 8) * 36 + ks4 * 8 + tg + 4];
#pragma unroll
                for (int nf = 0; nf < 8; nf++) {
                    uint32_t b0 = Vu[(ks * 8 + tg) * VS + nf * 8 + g];
                    uint32_t b1 = Vu[(ks * 8 + tg + 4) * VS + nf * 8 + g];
                    mma_tf32(oacc[nf], a0, a1, a2, a3, b0, b1);
                }
            }
        }
    }

    // epilogue
    float i0 = 1.f / l0, i1 = 1.f / l1;
    float* op = out + (long)b * SS * DM + h * HD;
#pragma unroll
    for (int nf = 0; nf < 8; nf++) {
        int c = nf * 8 + 2 * tg;
        float2 v0 = make_float2(oacc[nf][0] * i0, oacc[nf][1] * i0);
        float2 v1 = make_float2(oacc[nf][2] * i1, oacc[nf][3] * i1);
        *(float2*)(op + (long)rrow * DM + c) = v0;
        *(float2*)(op + (long)(rrow + 8) * DM + c) = v1;
    }
}

// ---------------------------------------------------------------------------
// TF32 GEMM v3: 2-stage cp.async raw ring + conversion pass with pair-
// permuted layouts; fragment loads are LDS.64; no inline cvt in the MMA loop.
//   rawA: 2 x 128x40 (converted IN PLACE to pair layout, per-row ownership)
//   rawB: 2 x  32x136
//   convB: 16x264 (pair rows (k,k+4) interleaved per column)
// Per iter: wait0; sync; issue t+1; convert stage t&1; sync; compute.
// ---------------------------------------------------------------------------
#define G_AS 40
#define G_BSR 136
#define G_BSC 264
#define G_ASTG (128 * G_AS)
#define G_BSTG (32 * G_BSR)
#define GEMM_SMEM ((2 * G_ASTG + 2 * G_BSTG + 16 * G_BSC) * 4)   // 92,672 B

template <bool RELU, bool BIAS, bool RES>
__global__ __launch_bounds__(256, 2) void mma_gemm3(
    const float* __restrict__ A, const float* __restrict__ Bm,
    const float* __restrict__ bias, const float* __restrict__ res,
    float* __restrict__ C, int K, int lda, int ldb, int ldc) {
    extern __shared__ float smem[];
    float* rawA = smem;
    float* rawB = smem + 2 * G_ASTG;
    float* convB = smem + 2 * G_ASTG + 2 * G_BSTG;

    int bm = blockIdx.y * 128;
    int bn = blockIdx.x * 128;
    int tid = threadIdx.x, warp = tid >> 5, lane = tid & 31;
    int g = lane >> 2, tg = lane & 3;
    int wm = warp >> 2, wn = warp & 3;

    const int am = tid >> 3;             // 0..31
    const int ak = (tid & 7) * 4;        // 0..28
    const int bk_ = tid >> 5;            // 0..7
    const int bn_ = (tid & 31) * 4;      // 0..124
    const int nT = K / 32;

    const float* Agp = A + (long)(bm + am) * lda + ak;
    const float* Bgp = Bm + (long)bk_ * ldb + bn + bn_;

    auto issue = [&](int t, int s) {
#pragma unroll
        for (int i = 0; i < 4; i++)
            cpa16(rawA + s * G_ASTG + (am + 32 * i) * G_AS + ak,
                  Agp + (long)32 * i * lda + t * 32);
#pragma unroll
        for (int i = 0; i < 4; i++)
            cpa16(rawB + s * G_BSTG + (bk_ + 8 * i) * G_BSR + bn_,
                  Bgp + (long)(t * 32 + 8 * i) * ldb);
        cpa_commit();
    };

    issue(0, 0);

    float acc[4][4][4];
#pragma unroll
    for (int i = 0; i < 4; i++)
#pragma unroll
        for (int j = 0; j < 4; j++)
#pragma unroll
            for (int c = 0; c < 4; c++) acc[i][j][c] = 0.f;

    // conversion ownership (constant per thread)
    const int arow = tid & 127;          // A row
    const int ag0 = (tid >> 7) * 2;      // A col-group base (of 4 groups)
    const int bp = tid & 15;             // B pair index 0..15
    const int bcg = tid >> 4;            // B col-group 0..15 (8 cols each)
    const int bkr = (bp >> 2) * 8 + (bp & 3);

    for (int t = 0; t < nT; t++) {
        int s = t & 1;
        cpa_wait0();
        __syncthreads();

        if (t + 1 < nT) issue(t + 1, s ^ 1);

        // --- conversion pass ---
        {
            float* Ap = rawA + s * G_ASTG;
#pragma unroll
            for (int gi = 0; gi < 2; gi++) {
                int G = ag0 + gi;
                float4 c0 = *(float4*)(Ap + arow * G_AS + 8 * G);
                float4 c1 = *(float4*)(Ap + arow * G_AS + 8 * G + 4);
                uint4 o0, o1;
                perm8(c0, c1, o0, o1);
                *(uint4*)(Ap + arow * G_AS + 8 * G) = o0;
                *(uint4*)(Ap + arow * G_AS + 8 * G + 4) = o1;
            }
            float* Bp = rawB + s * G_BSTG;
            float4 r0a = *(float4*)(Bp + bkr * G_BSR + 8 * bcg);
            float4 r0b = *(float4*)(Bp + bkr * G_BSR + 8 * bcg + 4);
            float4 r1a = *(float4*)(Bp + (bkr + 4) * G_BSR + 8 * bcg);
            float4 r1b = *(float4*)(Bp + (bkr + 4) * G_BSR + 8 * bcg + 4);
            uint4 q0, q1, q2, q3;
            perm8(make_float4(r0a.x, r1a.x, r0a.y, r1a.y),
                  make_float4(r0a.z, r1a.z, r0a.w, r1a.w), q0, q1);
            // perm8 above is just packing; build directly instead:
            q0 = make_uint4(f2tf(r0a.x), f2tf(r1a.x), f2tf(r0a.y), f2tf(r1a.y));
            q1 = make_uint4(f2tf(r0a.z), f2tf(r1a.z), f2tf(r0a.w), f2tf(r1a.w));
            q2 = make_uint4(f2tf(r0b.x), f2tf(r1b.x), f2tf(r0b.y), f2tf(r1b.y));
            q3 = make_uint4(f2tf(r0b.z), f2tf(r1b.z), f2tf(r0b.w), f2tf(r1b.w));
            uint4* dst = (uint4*)(convB + bp * G_BSC + 16 * bcg);
            dst[0] = q0; dst[1] = q1; dst[2] = q2; dst[3] = q3;
        }
        __syncthreads();

        const uint32_t* As = (const uint32_t*)(rawA + s * G_ASTG);
        const uint32_t* Bc = (const uint32_t*)convB;

#pragma unroll
        for (int ks = 0; ks < 4; ks++) {
            uint2 alo[4], ahi[4], bb[4];
#pragma unroll
            for (int mt = 0; mt < 4; mt++) {
                int r = wm * 64 + mt * 16 + g;
                alo[mt] = *(const uint2*)&As[r * G_AS + ks * 8 + 2 * tg];
                ahi[mt] = *(const uint2*)&As[(r + 8) * G_AS + ks * 8 + 2 * tg];
            }
#pragma unroll
            for (int nt = 0; nt < 4; nt++) {
                int c = wn * 32 + nt * 8 + g;
                bb[nt] = *(const uint2*)&Bc[(ks * 4 + tg) * G_BSC + 2 * c];
            }
#pragma unroll
            for (int mt = 0; mt < 4; mt++)
#pragma unroll
                for (int nt = 0; nt < 4; nt++)
                    mma_tf32(acc[mt][nt], alo[mt].x, ahi[mt].x, alo[mt].y,
                             ahi[mt].y, bb[nt].x, bb[nt].y);
        }
    }

    // epilogue
#pragma unroll
    for (int mt = 0; mt < 4; mt++) {
        int r = bm + wm * 64 + mt * 16 + g;
#pragma unroll
        for (int nt = 0; nt < 4; nt++) {
            int c = bn + wn * 32 + nt * 8 + tg * 2;
            float2 v0, v1;
            v0.x = acc[mt][nt][0]; v0.y = acc[mt][nt][1];
            v1.x = acc[mt][nt][2]; v1.y = acc[mt][nt][3];
            if (BIAS) {
                float2 bv = *(const float2*)(bias + c);
                v0.x += bv.x; v0.y += bv.y; v1.x += bv.x; v1.y += bv.y;
            }
            if (RELU) {
                v0.x = fmaxf(v0.x, 0.f); v0.y = fmaxf(v0.y, 0.f);
                v1.x = fmaxf(v1.x, 0.f); v1.y = fmaxf(v1.y, 0.f);
            }
            if (RES) {
                float2 r0 = *(const float2*)(res + (long)r * ldc + c);
                float2 r1 = *(const float2*)(res + (long)(r + 8) * ldc + c);
                v0.x += r0.x; v0.y += r0.y; v1.x += r1.x; v1.y += r1.y;
            }
            *(float2*)(C + (long)r * ldc + c) = v0;
            *(float2*)(C + (long)(r + 8) * ldc + c) = v1;
        }
    }
}

// ---------------------------------------------------------------------------
// Host side
// ---------------------------------------------------------------------------
template <typename T>
static float* sym(const T& s) {
    void* p = nullptr;
    cudaGetSymbolAddress(&p, s);
    return (float*)p;
}

extern "C" void kernel_launch(void* const* d_in, const int* in_sizes, int n_in,
                              void* d_out, int out_size) {
    const float* x      = (const float*)d_in[0];
    const int*   mask   = (const int*)d_in[1];
    const float* Wq     = (const float*)d_in[2];
    const float* bq     = (const float*)d_in[3];
    const float* Wk     = (const float*)d_in[4];
    const float* bk     = (const float*)d_in[5];
    const float* Wv     = (const float*)d_in[6];
    const float* bv     = (const float*)d_in[7];
    const float* Wo     = (const float*)d_in[8];
    const float* bo     = (const float*)d_in[9];
    const float* W1     = (const float*)d_in[10];
    const float* b1     = (const float*)d_in[11];
    const float* W2     = (const float*)d_in[12];
    const float* b2     = (const float*)d_in[13];
    const float* alpha1 = (const float*)d_in[14];
    const float* beta1  = (const float*)d_in[15];
    const float* alpha2 = (const float*)d_in[16];
    const float* beta2  = (const float*)d_in[17];
    float* out = (float*)d_out;

    float* n1   = sym(g_n1);
    float* qkv  = sym(g_qkv);
    float* wcat = sym(g_wcat);
    float* bcat = sym(g_bcat);
    float* attn = sym(g_attn);
    float* h    = sym(g_h);
    float* n2   = sym(g_n2);
    float* ffn  = sym(g_ffn);

    cudaFuncSetAttribute(mma_gemm3<false, true, false>,
                         cudaFuncAttributeMaxDynamicSharedMemorySize, GEMM_SMEM);
    cudaFuncSetAttribute(mma_gemm3<false, true, true>,
                         cudaFuncAttributeMaxDynamicSharedMemorySize, GEMM_SMEM);
    cudaFuncSetAttribute(mma_gemm3<true, true, false>,
                         cudaFuncAttributeMaxDynamicSharedMemorySize, GEMM_SMEM);
    cudaFuncSetAttribute(flash_kernel,
                         cudaFuncAttributeMaxDynamicSharedMemorySize, F_SMEM);

    // 0. concat QKV weights
    concat_w<<<(DM * 3 * DM) / 256, 256>>>(Wq, Wk, Wv, bq, bk, bv, wcat, bcat);

    // 1. LN1
    ln_kernel<<<NTOK, 256>>>(x, alpha1, beta1, n1);

    // 2. fused QKV projection: [4096,1024] @ [1024,3072] + bias
    {
        dim3 grid(3 * DM / 128, NTOK / 128, 1);
        mma_gemm3<false, true, false><<<grid, 256, GEMM_SMEM>>>(
            n1, wcat, bcat, nullptr, qkv, DM, DM, 3 * DM, 3 * DM);
    }

    // 3-5. flash attention
    {
        dim3 grid(SS / 128, HH, BB);
        flash_kernel<<<grid, 256, F_SMEM>>>(qkv, mask, attn);
    }

    // 6. h = x + attn @ Wo + bo
    {
        dim3 grid(DM / 128, NTOK / 128, 1);
        mma_gemm3<false, true, true><<<grid, 256, GEMM_SMEM>>>(
            attn, Wo, bo, x, h, DM, DM, DM, DM);
    }

    // 7. LN2
    ln_kernel<<<NTOK, 256>>>(h, alpha2, beta2, n2);

    // 8. ffn = relu(n2 @ W1 + b1)
    {
        dim3 grid(DF / 128, NTOK / 128, 1);
        mma_gemm3<true, true, false><<<grid, 256, GEMM_SMEM>>>(
            n2, W1, b1, nullptr, ffn, DM, DM, DF, DF);
    }

    // 9. out = h + ffn @ W2 + b2
    {
        dim3 grid(DM / 128, NTOK / 128, 1);
        mma_gemm3<false, true, true><<<grid, 256, GEMM_SMEM>>>(
            ffn, W2, b2, h, out, DF, DF, DM, DM);
    }
}

// round 12
// speedup vs baseline: 1.3585x; 1.3585x over previous
#include <cuda_runtime.h>
#include <cuda_bf16.h>
#include <math.h>
#include <stdint.h>

// Problem constants
#define BB 2
#define SS 2048
#define DM 1024
#define HH 16
#define HD 64
#define DF 4096
#define NTOK (BB * SS)          // 4096
#define NEGV (-1e9f)
#define EPS 1e-6f

// ---------------------------------------------------------------------------
// Scratch (device globals — no allocation allowed)
// ---------------------------------------------------------------------------
__device__ float g_n1[NTOK * DM];                // tf32, pair-permuted
__device__ float g_qkv[(long)NTOK * 3 * DM];     // raw fp32 (flash converts)
__device__ float g_wqkv[DM * 3 * DM];            // B' of Wq|Wk|Wv
__device__ float g_wo[DM * DM];                  // B' of Wo
__device__ float g_w1[DM * DF];                  // B' of W1
__device__ float g_w2[DF * DM];                  // B' of W2
__device__ float g_bcat[3 * DM];
__device__ float g_attn[NTOK * DM];              // tf32, pair-permuted
__device__ float g_h[NTOK * DM];                 // raw
__device__ float g_n2[NTOK * DM];                // tf32, pair-permuted
__device__ float g_ffn[(long)NTOK * DF];         // tf32, pair-permuted

// ---------------------------------------------------------------------------
// Helpers
// ---------------------------------------------------------------------------
__device__ __forceinline__ uint32_t f2tf(float f) {
    uint32_t u;
    asm("cvt.rna.tf32.f32 %0, %1;" : "=r"(u) : "f"(f));
    return u;
}
__device__ __forceinline__ float tff(float f) { return __uint_as_float(f2tf(f)); }
__device__ __forceinline__ uint4 cvt4(float4 v) {
    uint4 r;
    r.x = f2tf(v.x); r.y = f2tf(v.y); r.z = f2tf(v.z); r.w = f2tf(v.w);
    return r;
}
__device__ __forceinline__ void mma_tf32(float c[4], uint32_t a0, uint32_t a1,
                                         uint32_t a2, uint32_t a3,
                                         uint32_t b0, uint32_t b1) {
    asm volatile(
        "mma.sync.aligned.m16n8k8.row.col.f32.tf32.tf32.f32 "
        "{%0,%1,%2,%3}, {%4,%5,%6,%7}, {%8,%9}, {%0,%1,%2,%3};"
        : "+f"(c[0]), "+f"(c[1]), "+f"(c[2]), "+f"(c[3])
        : "r"(a0), "r"(a1), "r"(a2), "r"(a3), "r"(b0), "r"(b1));
}
__device__ __forceinline__ void cpa16(void* dst, const void* src) {
    uint32_t d = (uint32_t)__cvta_generic_to_shared(dst);
    asm volatile("cp.async.cg.shared.global [%0], [%1], 16;" :: "r"(d), "l"(src));
}
__device__ __forceinline__ void cpa_commit() {
    asm volatile("cp.async.commit_group;" ::: "memory");
}
__device__ __forceinline__ void cpa_wait0() {
    asm volatile("cp.async.wait_group 0;" ::: "memory");
}
__device__ __forceinline__ void cpa_wait1() {
    asm volatile("cp.async.wait_group 1;" ::: "memory");
}

// ---------------------------------------------------------------------------
// Weight prep: pair-permuted tf32 B' layout.
//   B'[((kt*16+q)*N + c)*2 + j] = tf32( W[kt*32 + (q>>2)*8 + (q&3) + 4j][c] )
// ---------------------------------------------------------------------------
__global__ __launch_bounds__(256) void prep_w(const float* __restrict__ W,
                                              float* __restrict__ out, int N) {
    long i = blockIdx.x * 256L + threadIdx.x;     // pair index
    int c = (int)(i % N);
    int ktq = (int)(i / N);
    int q = ktq & 15, kt = ktq >> 4;
    int r0 = kt * 32 + ((q >> 2) << 3) + (q & 3);
    float2 v;
    v.x = tff(W[(long)r0 * N + c]);
    v.y = tff(W[(long)(r0 + 4) * N + c]);
    *(float2*)(out + 2 * i) = v;
}

__global__ __launch_bounds__(256) void prep_wqkv(
    const float* __restrict__ Wq, const float* __restrict__ Wk,
    const float* __restrict__ Wv, float* __restrict__ out) {
    long i = blockIdx.x * 256L + threadIdx.x;     // pair index, N=3072
    int c = (int)(i % (3 * DM));
    int ktq = (int)(i / (3 * DM));
    int q = ktq & 15, kt = ktq >> 4;
    int r0 = kt * 32 + ((q >> 2) << 3) + (q & 3);
    const float* W = (c < DM) ? Wq : ((c < 2 * DM) ? Wk : Wv);
    int cc = c & (DM - 1);
    float2 v;
    v.x = tff(W[(long)r0 * DM + cc]);
    v.y = tff(W[(long)(r0 + 4) * DM + cc]);
    *(float2*)(out + 2 * i) = v;
}

__global__ __launch_bounds__(256) void concat_b(
    const float* __restrict__ bq, const float* __restrict__ bk,
    const float* __restrict__ bv, float* __restrict__ bcat) {
    int i = blockIdx.x * 256 + threadIdx.x;
    const float* b = (i < DM) ? bq : ((i < 2 * DM) ? bk : bv);
    bcat[i] = b[i & (DM - 1)];
}

// ---------------------------------------------------------------------------
// LayerNorm; output written tf32-rounded in pair-permuted layout.
// Thread t owns cols 4t..4t+3; base = row*DM + 8*(t>>1) + (t&1), positions
// base+0,2,4,6.
// ---------------------------------------------------------------------------
__global__ __launch_bounds__(256) void ln_kernel(const float* __restrict__ x,
                                                 const float* __restrict__ alpha,
                                                 const float* __restrict__ beta,
                                                 float* __restrict__ out) {
    long row = blockIdx.x;
    const float4* xr = (const float4*)(x + row * DM);
    float4 v = xr[threadIdx.x];

    float s  = v.x + v.y + v.z + v.w;
    float ss = v.x * v.x + v.y * v.y + v.z * v.z + v.w * v.w;

    __shared__ float sa[8], sb[8];
#pragma unroll
    for (int o = 16; o > 0; o >>= 1) {
        s  += __shfl_xor_sync(0xffffffffu, s, o);
        ss += __shfl_xor_sync(0xffffffffu, ss, o);
    }
    if ((threadIdx.x & 31) == 0) { sa[threadIdx.x >> 5] = s; sb[threadIdx.x >> 5] = ss; }
    __syncthreads();
    s = 0.f; ss = 0.f;
#pragma unroll
    for (int i = 0; i < 8; i++) { s += sa[i]; ss += sb[i]; }

    float mean = s * (1.0f / DM);
    float var  = (ss - (float)DM * mean * mean) * (1.0f / (DM - 1));
    var = fmaxf(var, 0.0f);
    float inv  = alpha[0] / (sqrtf(var) + EPS);
    float bta  = beta[0];

    int t = threadIdx.x;
    float* orow = out + row * DM + 8 * (t >> 1) + (t & 1);
    orow[0] = tff((v.x - mean) * inv + bta);
    orow[2] = tff((v.y - mean) * inv + bta);
    orow[4] = tff((v.z - mean) * inv + bta);
    orow[6] = tff((v.w - mean) * inv + bta);
}

// ---------------------------------------------------------------------------
// Flash attention (R9 v2 structure) — epilogue writes attn tf32-rounded in
// pair-permuted layout (attn is consumed only as a GEMM A operand).
// ---------------------------------------------------------------------------
#define KST 4864
#define VST 4608
#define F_KOFF 0
#define F_VOFF (2 * KST)
#define F_POFF (2 * KST + 2 * VST)
#define F_MOFF (F_POFF + 4608)
#define F_AOFF (F_MOFF + 128)
#define F_SMEM ((F_AOFF + 128) * 4)   // 95,744 B

__global__ __launch_bounds__(256, 2) void flash_kernel(
    const float* __restrict__ qkv, const int* __restrict__ mask,
    float* __restrict__ out) {
    constexpr int LDQ = 3 * DM;
    constexpr int KS = 76;
    constexpr int VS = 72;
    extern __shared__ float fsm[];
    float* Kst = fsm + F_KOFF;
    float* Vst = fsm + F_VOFF;
    uint32_t* Pst = (uint32_t*)(fsm + F_POFF);
    int* Mst = (int*)(fsm + F_MOFF);
    float* mAddF = fsm + F_AOFF;

    int qb = blockIdx.x * 128;
    int h  = blockIdx.y;
    int b  = blockIdx.z;
    const float* qp = qkv + (long)b * SS * LDQ + h * HD;
    const float* kp = qp + DM;
    const float* vp = qp + 2 * DM;
    const int* mp = mask + b * SS;

    int tid = threadIdx.x, warp = tid >> 5, lane = tid & 31;
    int g = lane >> 2, tg = lane & 3;
    int rrow = qb + warp * 16 + g;
    const int lr = tid >> 4;
    const int lc = (tid & 15) * 4;

    uint32_t qf[8][4];
#pragma unroll
    for (int ks = 0; ks < 8; ks++) {
        int c0 = ks * 8 + tg;
        qf[ks][0] = f2tf(0.125f * qp[(long)rrow * LDQ + c0]);
        qf[ks][1] = f2tf(0.125f * qp[(long)(rrow + 8) * LDQ + c0]);
        qf[ks][2] = f2tf(0.125f * qp[(long)rrow * LDQ + c0 + 4]);
        qf[ks][3] = f2tf(0.125f * qp[(long)(rrow + 8) * LDQ + c0 + 4]);
    }

    uint32_t* Psw = Pst + warp * 576;

    float m0 = -INFINITY, m1 = -INFINITY, l0 = 0.f, l1 = 0.f;
    float oacc[8][4];
#pragma unroll
    for (int nf = 0; nf < 8; nf++)
#pragma unroll
        for (int c = 0; c < 4; c++) oacc[nf][c] = 0.f;

    auto issue = [&](int t, int s) {
        int k0 = t * 64;
#pragma unroll
        for (int i = 0; i < 4; i++) {
            int row = lr + 16 * i;
            cpa16(Kst + s * KST + row * KS + lc, kp + (long)(k0 + row) * LDQ + lc);
            cpa16(Vst + s * VST + row * VS + lc, vp + (long)(k0 + row) * LDQ + lc);
        }
        if (tid < 16) cpa16(&Mst[s * 64 + tid * 4], &mp[k0 + tid * 4]);
        cpa_commit();
    };

    issue(0, 0);

    for (int t = 0; t < SS / 64; t++) {
        int s = t & 1;
        cpa_wait0();
        __syncthreads();

        if (t + 1 < SS / 64) issue(t + 1, s ^ 1);

        {
            float* Kp = Kst + s * KST;
            float* Vp = Vst + s * VST;
#pragma unroll
            for (int i = 0; i < 4; i++) {
                int row = lr + 16 * i;
                float4 k4 = *(float4*)(Kp + row * KS + lc);
                *(uint4*)(Kp + row * KS + lc) = cvt4(k4);
                float4 v4 = *(float4*)(Vp + row * VS + lc);
                *(uint4*)(Vp + row * VS + lc) = cvt4(v4);
            }
            if (tid < 64) mAddF[s * 64 + tid] = (Mst[s * 64 + tid] == 0) ? NEGV : 0.f;
        }
        __syncthreads();

        const uint32_t* Ku = (const uint32_t*)(Kst + s * KST);
        const uint32_t* Vu = (const uint32_t*)(Vst + s * VST);
        const float* mA = mAddF + s * 64;

        float sacc[8][4];
#pragma unroll
        for (int nf = 0; nf < 8; nf++)
#pragma unroll
            for (int c = 0; c < 4; c++) sacc[nf][c] = 0.f;
#pragma unroll
        for (int ks = 0; ks < 8; ks++) {
#pragma unroll
            for (int nf = 0; nf < 8; nf++) {
                int c = nf * 8 + g;
                uint32_t b0 = Ku[c * KS + ks * 8 + tg];
                uint32_t b1 = Ku[c * KS + ks * 8 + tg + 4];
                mma_tf32(sacc[nf], qf[ks][0], qf[ks][1], qf[ks][2], qf[ks][3], b0, b1);
            }
        }

        float tm0 = -INFINITY, tm1 = -INFINITY;
#pragma unroll
        for (int nf = 0; nf < 8; nf++) {
            float2 ma = *(const float2*)&mA[nf * 8 + 2 * tg];
            sacc[nf][0] += ma.x; sacc[nf][1] += ma.y;
            sacc[nf][2] += ma.x; sacc[nf][3] += ma.y;
            tm0 = fmaxf(tm0, fmaxf(sacc[nf][0], sacc[nf][1]));
            tm1 = fmaxf(tm1, fmaxf(sacc[nf][2], sacc[nf][3]));
        }
#pragma unroll
        for (int o = 1; o <= 2; o <<= 1) {
            tm0 = fmaxf(tm0, __shfl_xor_sync(0xffffffffu, tm0, o));
            tm1 = fmaxf(tm1, __shfl_xor_sync(0xffffffffu, tm1, o));
        }
        float nm0 = fmaxf(m0, tm0), nm1 = fmaxf(m1, tm1);
        float r0 = __expf(m0 - nm0), r1 = __expf(m1 - nm1);

        float s0 = 0.f, s1 = 0.f;
#pragma unroll
        for (int nf = 0; nf < 8; nf++) {
            sacc[nf][0] = __expf(sacc[nf][0] - nm0);
            sacc[nf][1] = __expf(sacc[nf][1] - nm0);
            sacc[nf][2] = __expf(sacc[nf][2] - nm1);
            sacc[nf][3] = __expf(sacc[nf][3] - nm1);
            s0 += sacc[nf][0] + sacc[nf][1];
            s1 += sacc[nf][2] + sacc[nf][3];
        }
#pragma unroll
        for (int o = 1; o <= 2; o <<= 1) {
            s0 += __shfl_xor_sync(0xffffffffu, s0, o);
            s1 += __shfl_xor_sync(0xffffffffu, s1, o);
        }
        l0 = l0 * r0 + s0; l1 = l1 * r1 + s1;
        m0 = nm0; m1 = nm1;
#pragma unroll
        for (int nf = 0; nf < 8; nf++) {
            oacc[nf][0] *= r0; oacc[nf][1] *= r0;
            oacc[nf][2] *= r1; oacc[nf][3] *= r1;
        }

#pragma unroll
        for (int half = 0; half < 2; half++) {
            __syncwarp();
#pragma unroll
            for (int nf4 = 0; nf4 < 4; nf4++) {
                int nf = half * 4 + nf4;
                *(uint2*)&Psw[g * 36 + nf4 * 8 + 2 * tg] =
                    make_uint2(f2tf(sacc[nf][0]), f2tf(sacc[nf][1]));
                *(uint2*)&Psw[(g + 8) * 36 + nf4 * 8 + 2 * tg] =
                    make_uint2(f2tf(sacc[nf][2]), f2tf(sacc[nf][3]));
            }
            __syncwarp();
#pragma unroll
            for (int ks4 = 0; ks4 < 4; ks4++) {
                int ks = half * 4 + ks4;
                uint32_t a0 = Psw[g * 36 + ks4 * 8 + tg];
                uint32_t a1 = Psw[(g + 8) * 36 + ks4 * 8 + tg];
                uint32_t a2 = Psw[g * 36 + ks4 * 8 + tg + 4];
                uint32_t a3 = Psw[(g + 8) * 36 + ks4 * 8 + tg + 4];
#pragma unroll
                for (int nf = 0; nf < 8; nf++) {
                    uint32_t b0 = Vu[(ks * 8 + tg) * VS + nf * 8 + g];
                    uint32_t b1 = Vu[(ks * 8 + tg + 4) * VS + nf * 8 + g];
                    mma_tf32(oacc[nf], a0, a1, a2, a3, b0, b1);
                }
            }
        }
    }

    // epilogue: pair-permuted tf32 store of attn
    float i0 = 1.f / l0, i1 = 1.f / l1;
    float* op = out + (long)b * SS * DM + h * HD;
    int p0 = (tg < 2) ? 4 * tg : 4 * tg - 7;   // pos within 8-group; p1 = p0+2
#pragma unroll
    for (int nf = 0; nf < 8; nf++) {
        int cb = nf * 8;
        op[(long)rrow * DM + cb + p0]       = tff(oacc[nf][0] * i0);
        op[(long)rrow * DM + cb + p0 + 2]   = tff(oacc[nf][1] * i0);
        op[(long)(rrow + 8) * DM + cb + p0]     = tff(oacc[nf][2] * i1);
        op[(long)(rrow + 8) * DM + cb + p0 + 2] = tff(oacc[nf][3] * i1);
    }
}

// ---------------------------------------------------------------------------
// TF32 GEMM v4: 3-stage cp.async ring, pre-converted operands, zero cvt in
// loop, all-LDS.64 fragment loads.
// ---------------------------------------------------------------------------
#define G_AS 40
#define G_BS 264
#define G_ASTG (128 * G_AS)
#define G_BSTG (16 * G_BS)
#define GEMM_SMEM ((3 * G_ASTG + 3 * G_BSTG) * 4)   // 112,128 B

template <bool RELU, bool BIAS, bool RES, bool PERM>
__global__ __launch_bounds__(256, 2) void mma_gemm4(
    const float* __restrict__ A, const float* __restrict__ Bw,
    const float* __restrict__ bias, const float* __restrict__ res,
    float* __restrict__ C, int K, int lda, int ldb, int ldc) {
    extern __shared__ float smem[];
    float* Ast = smem;
    float* Bst = smem + 3 * G_ASTG;

    int bm = blockIdx.y * 128;
    int bn = blockIdx.x * 128;
    int tid = threadIdx.x, warp = tid >> 5, lane = tid & 31;
    int g = lane >> 2, tg = lane & 3;
    int wm = warp >> 2, wn = warp & 3;

    const int am = tid >> 3;             // 0..31
    const int ak = (tid & 7) * 4;        // 0..28
    const int bq = tid >> 4;             // 0..15 (pair row)
    const int bj = (tid & 15) * 4;       // 0..60
    const int nT = K / 32;

    const float* Agp = A + (long)(bm + am) * lda + ak;

    auto issue = [&](int t, int s) {
#pragma unroll
        for (int i = 0; i < 4; i++)
            cpa16(Ast + s * G_ASTG + (am + 32 * i) * G_AS + ak,
                  Agp + (long)32 * i * lda + t * 32);
        const float* Bsrc = Bw + ((long)(t * 16 + bq) * ldb + bn) * 2 + bj;
#pragma unroll
        for (int i = 0; i < 4; i++)
            cpa16(Bst + s * G_BSTG + bq * G_BS + bj + 64 * i, Bsrc + 64 * i);
        cpa_commit();
    };

    issue(0, 0);
    issue(1, 1);

    float acc[4][4][4];
#pragma unroll
    for (int i = 0; i < 4; i++)
#pragma unroll
        for (int j = 0; j < 4; j++)
#pragma unroll
            for (int c = 0; c < 4; c++) acc[i][j][c] = 0.f;

    for (int t = 0; t < nT; t++) {
        cpa_wait1();
        __syncthreads();

        if (t + 2 < nT) issue(t + 2, (t + 2) % 3);
        else cpa_commit();   // keep wait_group accounting uniform

        const uint32_t* As = (const uint32_t*)(Ast + (t % 3) * G_ASTG);
        const uint32_t* Bc = (const uint32_t*)(Bst + (t % 3) * G_BSTG);

#pragma unroll
        for (int ks = 0; ks < 4; ks++) {
            uint2 alo[4], ahi[4], bb[4];
#pragma unroll
            for (int mt = 0; mt < 4; mt++) {
                int r = wm * 64 + mt * 16 + g;
                alo[mt] = *(const uint2*)&As[r * G_AS + ks * 8 + 2 * tg];
                ahi[mt] = *(const uint2*)&As[(r + 8) * G_AS + ks * 8 + 2 * tg];
            }
#pragma unroll
            for (int nt = 0; nt < 4; nt++) {
                int c = wn * 32 + nt * 8 + g;
                bb[nt] = *(const uint2*)&Bc[(ks * 4 + tg) * G_BS + 2 * c];
            }
#pragma unroll
            for (int mt = 0; mt < 4; mt++)
#pragma unroll
                for (int nt = 0; nt < 4; nt++)
                    mma_tf32(acc[mt][nt], alo[mt].x, ahi[mt].x, alo[mt].y,
                             ahi[mt].y, bb[nt].x, bb[nt].y);
        }
    }

    // epilogue
    int p0 = (tg < 2) ? 4 * tg : 4 * tg - 7;
#pragma unroll
    for (int mt = 0; mt < 4; mt++) {
        int r = bm + wm * 64 + mt * 16 + g;
#pragma unroll
        for (int nt = 0; nt < 4; nt++) {
            int cb = bn + wn * 32 + nt * 8;
            int c = cb + tg * 2;
            float v0 = acc[mt][nt][0], v1 = acc[mt][nt][1];
            float v2 = acc[mt][nt][2], v3 = acc[mt][nt][3];
            if (BIAS) {
                float2 bv = *(const float2*)(bias + c);
                v0 += bv.x; v1 += bv.y; v2 += bv.x; v3 += bv.y;
            }
            if (RELU) {
                v0 = fmaxf(v0, 0.f); v1 = fmaxf(v1, 0.f);
                v2 = fmaxf(v2, 0.f); v3 = fmaxf(v3, 0.f);
            }
            if (RES) {
                float2 r0 = *(const float2*)(res + (long)r * ldc + c);
                float2 r1 = *(const float2*)(res + (long)(r + 8) * ldc + c);
                v0 += r0.x; v1 += r0.y; v2 += r1.x; v3 += r1.y;
            }
            if (PERM) {
                C[(long)r * ldc + cb + p0]       = tff(v0);
                C[(long)r * ldc + cb + p0 + 2]   = tff(v1);
                C[(long)(r + 8) * ldc + cb + p0]     = tff(v2);
                C[(long)(r + 8) * ldc + cb + p0 + 2] = tff(v3);
            } else {
                *(float2*)(C + (long)r * ldc + c) = make_float2(v0, v1);
                *(float2*)(C + (long)(r + 8) * ldc + c) = make_float2(v2, v3);
            }
        }
    }
}

// ---------------------------------------------------------------------------
// Host side
// ---------------------------------------------------------------------------
template <typename T>
static float* sym(const T& s) {
    void* p = nullptr;
    cudaGetSymbolAddress(&p, s);
    return (float*)p;
}

extern "C" void kernel_launch(void* const* d_in, const int* in_sizes, int n_in,
                              void* d_out, int out_size) {
    const float* x      = (const float*)d_in[0];
    const int*   mask   = (const int*)d_in[1];
    const float* Wq     = (const float*)d_in[2];
    const float* bq     = (const float*)d_in[3];
    const float* Wk     = (const float*)d_in[4];
    const float* bk     = (const float*)d_in[5];
    const float* Wv     = (const float*)d_in[6];
    const float* bv     = (const float*)d_in[7];
    const float* Wo     = (const float*)d_in[8];
    const float* bo     = (const float*)d_in[9];
    const float* W1     = (const float*)d_in[10];
    const float* b1     = (const float*)d_in[11];
    const float* W2     = (const float*)d_in[12];
    const float* b2     = (const float*)d_in[13];
    const float* alpha1 = (const float*)d_in[14];
    const float* beta1  = (const float*)d_in[15];
    const float* alpha2 = (const float*)d_in[16];
    const float* beta2  = (const float*)d_in[17];
    float* out = (float*)d_out;

    float* n1   = sym(g_n1);
    float* qkv  = sym(g_qkv);
    float* wqkv = sym(g_wqkv);
    float* wo   = sym(g_wo);
    float* w1   = sym(g_w1);
    float* w2   = sym(g_w2);
    float* bcat = sym(g_bcat);
    float* attn = sym(g_attn);
    float* h    = sym(g_h);
    float* n2   = sym(g_n2);
    float* ffn  = sym(g_ffn);

    cudaFuncSetAttribute(mma_gemm4<false, true, false, false>,
                         cudaFuncAttributeMaxDynamicSharedMemorySize, GEMM_SMEM);
    cudaFuncSetAttribute(mma_gemm4<false, true, true, false>,
                         cudaFuncAttributeMaxDynamicSharedMemorySize, GEMM_SMEM);
    cudaFuncSetAttribute(mma_gemm4<true, true, false, true>,
                         cudaFuncAttributeMaxDynamicSharedMemorySize, GEMM_SMEM);
    cudaFuncSetAttribute(flash_kernel,
                         cudaFuncAttributeMaxDynamicSharedMemorySize, F_SMEM);

    // 0. weight prep (pair-permuted tf32 B' layouts) + bias concat
    prep_wqkv<<<(DM * 3 * DM / 2) / 256, 256>>>(Wq, Wk, Wv, wqkv);
    prep_w<<<(DM * DM / 2) / 256, 256>>>(Wo, wo, DM);
    prep_w<<<(DM * DF / 2) / 256, 256>>>(W1, w1, DF);
    prep_w<<<(DF * DM / 2) / 256, 256>>>(W2, w2, DM);
    concat_b<<<12, 256>>>(bq, bk, bv, bcat);

    // 1. LN1 -> n1 (permuted tf32)
    ln_kernel<<<NTOK, 256>>>(x, alpha1, beta1, n1);

    // 2. fused QKV projection -> qkv raw
    {
        dim3 grid(3 * DM / 128, NTOK / 128, 1);
        mma_gemm4<false, true, false, false><<<grid, 256, GEMM_SMEM>>>(
            n1, wqkv, bcat, nullptr, qkv, DM, DM, 3 * DM, 3 * DM);
    }

    // 3-5. flash attention -> attn (permuted tf32)
    {
        dim3 grid(SS / 128, HH, BB);
        flash_kernel<<<grid, 256, F_SMEM>>>(qkv, mask, attn);
    }

    // 6. h = x + attn @ Wo + bo   (raw)
    {
        dim3 grid(DM / 128, NTOK / 128, 1);
        mma_gemm4<false, true, true, false><<<grid, 256, GEMM_SMEM>>>(
            attn, wo, bo, x, h, DM, DM, DM, DM);
    }

    // 7. LN2 -> n2 (permuted tf32)
    ln_kernel<<<NTOK, 256>>>(h, alpha2, beta2, n2);

    // 8. ffn = relu(n2 @ W1 + b1)  -> permuted tf32
    {
        dim3 grid(DF / 128, NTOK / 128, 1);
        mma_gemm4<true, true, false, true><<<grid, 256, GEMM_SMEM>>>(
            n2, w1, b1, nullptr, ffn, DM, DM, DF, DF);
    }

    // 9. out = h + ffn @ W2 + b2   (raw)
    {
        dim3 grid(DM / 128, NTOK / 128, 1);
        mma_gemm4<false, true, true, false><<<grid, 256, GEMM_SMEM>>>(
            ffn, w2, b2, h, out, DF, DF, DM, DM);
    }
}

// round 14
// speedup vs baseline: 1.6147x; 1.1886x over previous
#include <cuda_runtime.h>
#include <cuda_fp16.h>
#include <math.h>
#include <stdint.h>

// Problem constants
#define BB 2
#define SS 2048
#define DM 1024
#define HH 16
#define HD 64
#define DF 4096
#define NTOK (BB * SS)          // 4096
#define NEGV (-1e9f)
#define EPS 1e-6f

// ---------------------------------------------------------------------------
// Scratch (device globals — no allocation allowed)
// ---------------------------------------------------------------------------
__device__ __half g_n1[NTOK * DM];                 // fp16 rows
__device__ float  g_qkv[(long)NTOK * 3 * DM];      // raw fp32 (flash input)
__device__ __half g_wqkvT[3 * DM * DM];            // [3072][1024] W^T fp16
__device__ __half g_woT[DM * DM];                  // [1024][1024]
__device__ __half g_w1T[(long)DF * DM];            // [4096][1024]
__device__ __half g_w2T[(long)DM * DF];            // [1024][4096]
__device__ float  g_bcat[3 * DM];
__device__ __half g_attn[NTOK * DM];               // fp16 rows
__device__ float  g_h[NTOK * DM];                  // raw fp32 (residual+LN2)
__device__ __half g_n2[NTOK * DM];                 // fp16 rows
__device__ __half g_ffn[(long)NTOK * DF];          // fp16 rows

// ---------------------------------------------------------------------------
// Helpers
// ---------------------------------------------------------------------------
__device__ __forceinline__ uint32_t f2tf(float f) {
    uint32_t u;
    asm("cvt.rna.tf32.f32 %0, %1;" : "=r"(u) : "f"(f));
    return u;
}
__device__ __forceinline__ uint4 cvt4(float4 v) {
    uint4 r;
    r.x = f2tf(v.x); r.y = f2tf(v.y); r.z = f2tf(v.z); r.w = f2tf(v.w);
    return r;
}
// tf32 legacy mma (flash kernel)
__device__ __forceinline__ void mma_tf32(float c[4], uint32_t a0, uint32_t a1,
                                         uint32_t a2, uint32_t a3,
                                         uint32_t b0, uint32_t b1) {
    asm volatile(
        "mma.sync.aligned.m16n8k8.row.col.f32.tf32.tf32.f32 "
        "{%0,%1,%2,%3}, {%4,%5,%6,%7}, {%8,%9}, {%0,%1,%2,%3};"
        : "+f"(c[0]), "+f"(c[1]), "+f"(c[2]), "+f"(c[3])
        : "r"(a0), "r"(a1), "r"(a2), "r"(a3), "r"(b0), "r"(b1));
}
// fp16 mma with fp32 accumulate (GEMMs)
__device__ __forceinline__ void mma_f16(float c[4], uint32_t a0, uint32_t a1,
                                        uint32_t a2, uint32_t a3,
                                        uint32_t b0, uint32_t b1) {
    asm volatile(
        "mma.sync.aligned.m16n8k16.row.col.f32.f16.f16.f32 "
        "{%0,%1,%2,%3}, {%4,%5,%6,%7}, {%8,%9}, {%0,%1,%2,%3};"
        : "+f"(c[0]), "+f"(c[1]), "+f"(c[2]), "+f"(c[3])
        : "r"(a0), "r"(a1), "r"(a2), "r"(a3), "r"(b0), "r"(b1));
}
__device__ __forceinline__ void cpa16(void* dst, const void* src) {
    uint32_t d = (uint32_t)__cvta_generic_to_shared(dst);
    asm volatile("cp.async.cg.shared.global [%0], [%1], 16;" :: "r"(d), "l"(src));
}
__device__ __forceinline__ void cpa_commit() {
    asm volatile("cp.async.commit_group;" ::: "memory");
}
__device__ __forceinline__ void cpa_wait0() {
    asm volatile("cp.async.wait_group 0;" ::: "memory");
}
__device__ __forceinline__ void cpa_wait1() {
    asm volatile("cp.async.wait_group 1;" ::: "memory");
}

// ---------------------------------------------------------------------------
// Weight transpose prep: out[(rowOff+n)*K + k] = fp16(W[k*N + n])
// block (32,8); grid (N/32, K/32)
// ---------------------------------------------------------------------------
__global__ void prep_wT(const float* __restrict__ W, __half* __restrict__ out,
                        int K, int N, int rowOff) {
    __shared__ float t[32][33];
    int n0 = blockIdx.x * 32, k0 = blockIdx.y * 32;
    int tx = threadIdx.x, ty = threadIdx.y;
#pragma unroll
    for (int i = 0; i < 4; i++)
        t[ty + 8 * i][tx] = W[(long)(k0 + ty + 8 * i) * N + n0 + tx];
    __syncthreads();
#pragma unroll
    for (int i = 0; i < 4; i++)
        out[(long)(rowOff + n0 + ty + 8 * i) * K + k0 + tx] =
            __float2half_rn(t[tx][ty + 8 * i]);
}

__global__ __launch_bounds__(256) void concat_b(
    const float* __restrict__ bq, const float* __restrict__ bk,
    const float* __restrict__ bv, float* __restrict__ bcat) {
    int i = blockIdx.x * 256 + threadIdx.x;
    const float* b = (i < DM) ? bq : ((i < 2 * DM) ? bk : bv);
    bcat[i] = b[i & (DM - 1)];
}

// ---------------------------------------------------------------------------
// LayerNorm -> fp16 rows
// ---------------------------------------------------------------------------
__global__ __launch_bounds__(256) void ln_kernel(const float* __restrict__ x,
                                                 const float* __restrict__ alpha,
                                                 const float* __restrict__ beta,
                                                 __half* __restrict__ out) {
    long row = blockIdx.x;
    const float4* xr = (const float4*)(x + row * DM);
    float4 v = xr[threadIdx.x];

    float s  = v.x + v.y + v.z + v.w;
    float ss = v.x * v.x + v.y * v.y + v.z * v.z + v.w * v.w;

    __shared__ float sa[8], sb[8];
#pragma unroll
    for (int o = 16; o > 0; o >>= 1) {
        s  += __shfl_xor_sync(0xffffffffu, s, o);
        ss += __shfl_xor_sync(0xffffffffu, ss, o);
    }
    if ((threadIdx.x & 31) == 0) { sa[threadIdx.x >> 5] = s; sb[threadIdx.x >> 5] = ss; }
    __syncthreads();
    s = 0.f; ss = 0.f;
#pragma unroll
    for (int i = 0; i < 8; i++) { s += sa[i]; ss += sb[i]; }

    float mean = s * (1.0f / DM);
    float var  = (ss - (float)DM * mean * mean) * (1.0f / (DM - 1));
    var = fmaxf(var, 0.0f);
    float inv  = alpha[0] / (sqrtf(var) + EPS);
    float bta  = beta[0];

    __half2 h0 = __floats2half2_rn((v.x - mean) * inv + bta, (v.y - mean) * inv + bta);
    __half2 h1 = __floats2half2_rn((v.z - mean) * inv + bta, (v.w - mean) * inv + bta);
    __half2* orow = (__half2*)(out + row * DM) + 2 * threadIdx.x;
    orow[0] = h0;
    orow[1] = h1;
}

// ---------------------------------------------------------------------------
// Flash attention (R12 structure, tf32 internals, fp32 qkv in, fp16 attn out)
// ---------------------------------------------------------------------------
#define KST 4864
#define VST 4608
#define F_KOFF 0
#define F_VOFF (2 * KST)
#define F_POFF (2 * KST + 2 * VST)
#define F_MOFF (F_POFF + 4608)
#define F_AOFF (F_MOFF + 128)
#define F_SMEM ((F_AOFF + 128) * 4)   // 95,744 B

__global__ __launch_bounds__(256, 2) void flash_kernel(
    const float* __restrict__ qkv, const int* __restrict__ mask,
    __half* __restrict__ out) {
    constexpr int LDQ = 3 * DM;
    constexpr int KS = 76;
    constexpr int VS = 72;
    extern __shared__ float fsm[];
    float* Kst = fsm + F_KOFF;
    float* Vst = fsm + F_VOFF;
    uint32_t* Pst = (uint32_t*)(fsm + F_POFF);
    int* Mst = (int*)(fsm + F_MOFF);
    float* mAddF = fsm + F_AOFF;

    int qb = blockIdx.x * 128;
    int h  = blockIdx.y;
    int b  = blockIdx.z;
    const float* qp = qkv + (long)b * SS * LDQ + h * HD;
    const float* kp = qp + DM;
    const float* vp = qp + 2 * DM;
    const int* mp = mask + b * SS;

    int tid = threadIdx.x, warp = tid >> 5, lane = tid & 31;
    int g = lane >> 2, tg = lane & 3;
    int rrow = qb + warp * 16 + g;
    const int lr = tid >> 4;
    const int lc = (tid & 15) * 4;

    uint32_t qf[8][4];
#pragma unroll
    for (int ks = 0; ks < 8; ks++) {
        int c0 = ks * 8 + tg;
        qf[ks][0] = f2tf(0.125f * qp[(long)rrow * LDQ + c0]);
        qf[ks][1] = f2tf(0.125f * qp[(long)(rrow + 8) * LDQ + c0]);
        qf[ks][2] = f2tf(0.125f * qp[(long)rrow * LDQ + c0 + 4]);
        qf[ks][3] = f2tf(0.125f * qp[(long)(rrow + 8) * LDQ + c0 + 4]);
    }

    uint32_t* Psw = Pst + warp * 576;

    float m0 = -INFINITY, m1 = -INFINITY, l0 = 0.f, l1 = 0.f;
    float oacc[8][4];
#pragma unroll
    for (int nf = 0; nf < 8; nf++)
#pragma unroll
        for (int c = 0; c < 4; c++) oacc[nf][c] = 0.f;

    auto issue = [&](int t, int s) {
        int k0 = t * 64;
#pragma unroll
        for (int i = 0; i < 4; i++) {
            int row = lr + 16 * i;
            cpa16(Kst + s * KST + row * KS + lc, kp + (long)(k0 + row) * LDQ + lc);
            cpa16(Vst + s * VST + row * VS + lc, vp + (long)(k0 + row) * LDQ + lc);
        }
        if (tid < 16) cpa16(&Mst[s * 64 + tid * 4], &mp[k0 + tid * 4]);
        cpa_commit();
    };

    issue(0, 0);

    for (int t = 0; t < SS / 64; t++) {
        int s = t & 1;
        cpa_wait0();
        __syncthreads();

        if (t + 1 < SS / 64) issue(t + 1, s ^ 1);

        {
            float* Kp = Kst + s * KST;
            float* Vp = Vst + s * VST;
#pragma unroll
            for (int i = 0; i < 4; i++) {
                int row = lr + 16 * i;
                float4 k4 = *(float4*)(Kp + row * KS + lc);
                *(uint4*)(Kp + row * KS + lc) = cvt4(k4);
                float4 v4 = *(float4*)(Vp + row * VS + lc);
                *(uint4*)(Vp + row * VS + lc) = cvt4(v4);
            }
            if (tid < 64) mAddF[s * 64 + tid] = (Mst[s * 64 + tid] == 0) ? NEGV : 0.f;
        }
        __syncthreads();

        const uint32_t* Ku = (const uint32_t*)(Kst + s * KST);
        const uint32_t* Vu = (const uint32_t*)(Vst + s * VST);
        const float* mA = mAddF + s * 64;

        float sacc[8][4];
#pragma unroll
        for (int nf = 0; nf < 8; nf++)
#pragma unroll
            for (int c = 0; c < 4; c++) sacc[nf][c] = 0.f;
#pragma unroll
        for (int ks = 0; ks < 8; ks++) {
#pragma unroll
            for (int nf = 0; nf < 8; nf++) {
                int c = nf * 8 + g;
                uint32_t b0 = Ku[c * KS + ks * 8 + tg];
                uint32_t b1 = Ku[c * KS + ks * 8 + tg + 4];
                mma_tf32(sacc[nf], qf[ks][0], qf[ks][1], qf[ks][2], qf[ks][3], b0, b1);
            }
        }

        float tm0 = -INFINITY, tm1 = -INFINITY;
#pragma unroll
        for (int nf = 0; nf < 8; nf++) {
            float2 ma = *(const float2*)&mA[nf * 8 + 2 * tg];
            sacc[nf][0] += ma.x; sacc[nf][1] += ma.y;
            sacc[nf][2] += ma.x; sacc[nf][3] += ma.y;
            tm0 = fmaxf(tm0, fmaxf(sacc[nf][0], sacc[nf][1]));
            tm1 = fmaxf(tm1, fmaxf(sacc[nf][2], sacc[nf][3]));
        }
#pragma unroll
        for (int o = 1; o <= 2; o <<= 1) {
            tm0 = fmaxf(tm0, __shfl_xor_sync(0xffffffffu, tm0, o));
            tm1 = fmaxf(tm1, __shfl_xor_sync(0xffffffffu, tm1, o));
        }
        float nm0 = fmaxf(m0, tm0), nm1 = fmaxf(m1, tm1);
        float r0 = __expf(m0 - nm0), r1 = __expf(m1 - nm1);

        float s0 = 0.f, s1 = 0.f;
#pragma unroll
        for (int nf = 0; nf < 8; nf++) {
            sacc[nf][0] = __expf(sacc[nf][0] - nm0);
            sacc[nf][1] = __expf(sacc[nf][1] - nm0);
            sacc[nf][2] = __expf(sacc[nf][2] - nm1);
            sacc[nf][3] = __expf(sacc[nf][3] - nm1);
            s0 += sacc[nf][0] + sacc[nf][1];
            s1 += sacc[nf][2] + sacc[nf][3];
        }
#pragma unroll
        for (int o = 1; o <= 2; o <<= 1) {
            s0 += __shfl_xor_sync(0xffffffffu, s0, o);
            s1 += __shfl_xor_sync(0xffffffffu, s1, o);
        }
        l0 = l0 * r0 + s0; l1 = l1 * r1 + s1;
        m0 = nm0; m1 = nm1;
#pragma unroll
        for (int nf = 0; nf < 8; nf++) {
            oacc[nf][0] *= r0; oacc[nf][1] *= r0;
            oacc[nf][2] *= r1; oacc[nf][3] *= r1;
        }

#pragma unroll
        for (int half = 0; half < 2; half++) {
            __syncwarp();
#pragma unroll
            for (int nf4 = 0; nf4 < 4; nf4++) {
                int nf = half * 4 + nf4;
                *(uint2*)&Psw[g * 36 + nf4 * 8 + 2 * tg] =
                    make_uint2(f2tf(sacc[nf][0]), f2tf(sacc[nf][1]));
                *(uint2*)&Psw[(g + 8) * 36 + nf4 * 8 + 2 * tg] =
                    make_uint2(f2tf(sacc[nf][2]), f2tf(sacc[nf][3]));
            }
            __syncwarp();
#pragma unroll
            for (int ks4 = 0; ks4 < 4; ks4++) {
                int ks = half * 4 + ks4;
                uint32_t a0 = Psw[g * 36 + ks4 * 8 + tg];
                uint32_t a1 = Psw[(g + 8) * 36 + ks4 * 8 + tg];
                uint32_t a2 = Psw[g * 36 + ks4 * 8 + tg + 4];
                uint32_t a3 = Psw[(g + 8) * 36 + ks4 * 8 + tg + 4];
#pragma unroll
                for (int nf = 0; nf < 8; nf++) {
                    uint32_t b0 = Vu[(ks * 8 + tg) * VS + nf * 8 + g];
                    uint32_t b1 = Vu[(ks * 8 + tg + 4) * VS + nf * 8 + g];
                    mma_tf32(oacc[nf], a0, a1, a2, a3, b0, b1);
                }
            }
        }
    }

    // epilogue: fp16 stores (attn consumed only as a GEMM A operand)
    float i0 = 1.f / l0, i1 = 1.f / l1;
    __half* op = out + (long)b * SS * DM + h * HD;
#pragma unroll
    for (int nf = 0; nf < 8; nf++) {
        int c = nf * 8 + 2 * tg;
        *(__half2*)(op + (long)rrow * DM + c) =
            __floats2half2_rn(oacc[nf][0] * i0, oacc[nf][1] * i0);
        *(__half2*)(op + (long)(rrow + 8) * DM + c) =
            __floats2half2_rn(oacc[nf][2] * i1, oacc[nf][3] * i1);
    }
}

// ---------------------------------------------------------------------------
// fp16 GEMM v5: 3-stage cp.async ring.  C = A @ Bt^T (+bias)(relu)(+res)
// A  half [M][K] row-major; Bt half [N][K] row-major (transposed weight).
// BM=BN=128, BK=32, 256 threads, 8 warps 2x4, warp tile 64x32 (MT=4, NT=4).
// Smem half tiles [128][40] (stride 20 words: frag phases bank-bijective).
// Per k16 step: 16 mma.m16n8k16 : 24 LDS.32.
// ---------------------------------------------------------------------------
#define H_AS 40
#define H_STG (128 * H_AS)                         // halves per tile-stage
#define GEMM_SMEM (3 * 2 * H_STG * 2)              // 61,440 B

template <bool RELU, bool RES, bool OUTH>
__global__ __launch_bounds__(256, 2) void h_gemm(
    const __half* __restrict__ A, const __half* __restrict__ Bt,
    const float* __restrict__ bias, const float* __restrict__ res,
    float* __restrict__ C, __half* __restrict__ Ch, int K, int ldc) {
    extern __shared__ __half hsm[];
    __half* Ast = hsm;
    __half* Bst = hsm + 3 * H_STG;

    int bm = blockIdx.y * 128;
    int bn = blockIdx.x * 128;
    int tid = threadIdx.x, warp = tid >> 5, lane = tid & 31;
    int g = lane >> 2, tg = lane & 3;
    int wm = warp >> 2, wn = warp & 3;

    const int ar = tid >> 1;            // 0..127 row
    const int ac = (tid & 1) * 16;      // half-offset of first 16B chunk pair
    const int nT = K / 32;

    auto issue = [&](int t, int s) {
        const __half* Ag = A + (long)(bm + ar) * K + t * 32 + ac;
        const __half* Bg = Bt + (long)(bn + ar) * K + t * 32 + ac;
        __half* Aw = Ast + s * H_STG + ar * H_AS + ac;
        __half* Bw = Bst + s * H_STG + ar * H_AS + ac;
        cpa16(Aw, Ag);
        cpa16(Aw + 8, Ag + 8);
        cpa16(Bw, Bg);
        cpa16(Bw + 8, Bg + 8);
        cpa_commit();
    };

    issue(0, 0);
    issue(1, 1);

    float acc[4][4][4];
#pragma unroll
    for (int i = 0; i < 4; i++)
#pragma unroll
        for (int j = 0; j < 4; j++)
#pragma unroll
            for (int c = 0; c < 4; c++) acc[i][j][c] = 0.f;

    for (int t = 0; t < nT; t++) {
        cpa_wait1();
        __syncthreads();

        if (t + 2 < nT) issue(t + 2, (t + 2) % 3);
        else cpa_commit();

        const uint32_t* As = (const uint32_t*)(Ast + (t % 3) * H_STG);
        const uint32_t* Bs = (const uint32_t*)(Bst + (t % 3) * H_STG);

#pragma unroll
        for (int ks = 0; ks < 2; ks++) {
            uint32_t af[4][4];
            uint32_t bf[4][2];
#pragma unroll
            for (int mt = 0; mt < 4; mt++) {
                int r = wm * 64 + mt * 16 + g;
                af[mt][0] = As[r * 20 + ks * 8 + tg];
                af[mt][1] = As[(r + 8) * 20 + ks * 8 + tg];
                af[mt][2] = As[r * 20 + ks * 8 + 4 + tg];
                af[mt][3] = As[(r + 8) * 20 + ks * 8 + 4 + tg];
            }
#pragma unroll
            for (int nt = 0; nt < 4; nt++) {
                int c = wn * 32 + nt * 8 + g;
                bf[nt][0] = Bs[c * 20 + ks * 8 + tg];
                bf[nt][1] = Bs[c * 20 + ks * 8 + 4 + tg];
            }
#pragma unroll
            for (int mt = 0; mt < 4; mt++)
#pragma unroll
                for (int nt = 0; nt < 4; nt++)
                    mma_f16(acc[mt][nt], af[mt][0], af[mt][1], af[mt][2],
                            af[mt][3], bf[nt][0], bf[nt][1]);
        }
    }

    // epilogue
#pragma unroll
    for (int mt = 0; mt < 4; mt++) {
        int r = bm + wm * 64 + mt * 16 + g;
#pragma unroll
        for (int nt = 0; nt < 4; nt++) {
            int c = bn + wn * 32 + nt * 8 + tg * 2;
            float v0 = acc[mt][nt][0], v1 = acc[mt][nt][1];
            float v2 = acc[mt][nt][2], v3 = acc[mt][nt][3];
            {
                float2 bv = *(const float2*)(bias + c);
                v0 += bv.x; v1 += bv.y; v2 += bv.x; v3 += bv.y;
            }
            if (RELU) {
                v0 = fmaxf(v0, 0.f); v1 = fmaxf(v1, 0.f);
                v2 = fmaxf(v2, 0.f); v3 = fmaxf(v3, 0.f);
            }
            if (RES) {
                float2 r0 = *(const float2*)(res + (long)r * ldc + c);
                float2 r1 = *(const float2*)(res + (long)(r + 8) * ldc + c);
                v0 += r0.x; v1 += r0.y; v2 += r1.x; v3 += r1.y;
            }
            if (OUTH) {
                *(__half2*)(Ch + (long)r * ldc + c) = __floats2half2_rn(v0, v1);
                *(__half2*)(Ch + (long)(r + 8) * ldc + c) = __floats2half2_rn(v2, v3);
            } else {
                *(float2*)(C + (long)r * ldc + c) = make_float2(v0, v1);
                *(float2*)(C + (long)(r + 8) * ldc + c) = make_float2(v2, v3);
            }
        }
    }
}

// ---------------------------------------------------------------------------
// Host side
// ---------------------------------------------------------------------------
template <typename T>
static void* symv(const T& s) {
    void* p = nullptr;
    cudaGetSymbolAddress(&p, s);
    return p;
}

extern "C" void kernel_launch(void* const* d_in, const int* in_sizes, int n_in,
                              void* d_out, int out_size) {
    const float* x      = (const float*)d_in[0];
    const int*   mask   = (const int*)d_in[1];
    const float* Wq     = (const float*)d_in[2];
    const float* bq     = (const float*)d_in[3];
    const float* Wk     = (const float*)d_in[4];
    const float* bk     = (const float*)d_in[5];
    const float* Wv     = (const float*)d_in[6];
    const float* bv     = (const float*)d_in[7];
    const float* Wo     = (const float*)d_in[8];
    const float* bo     = (const float*)d_in[9];
    const float* W1     = (const float*)d_in[10];
    const float* b1     = (const float*)d_in[11];
    const float* W2     = (const float*)d_in[12];
    const float* b2     = (const float*)d_in[13];
    const float* alpha1 = (const float*)d_in[14];
    const float* beta1  = (const float*)d_in[15];
    const float* alpha2 = (const float*)d_in[16];
    const float* beta2  = (const float*)d_in[17];
    float* out = (float*)d_out;

    __half* n1    = (__half*)symv(g_n1);
    float*  qkv   = (float*)symv(g_qkv);
    __half* wqkvT = (__half*)symv(g_wqkvT);
    __half* woT   = (__half*)symv(g_woT);
    __half* w1T   = (__half*)symv(g_w1T);
    __half* w2T   = (__half*)symv(g_w2T);
    float*  bcat  = (float*)symv(g_bcat);
    __half* attn  = (__half*)symv(g_attn);
    float*  h     = (float*)symv(g_h);
    __half* n2    = (__half*)symv(g_n2);
    __half* ffn   = (__half*)symv(g_ffn);

    cudaFuncSetAttribute(h_gemm<false, false, false>,
                         cudaFuncAttributeMaxDynamicSharedMemorySize, GEMM_SMEM);
    cudaFuncSetAttribute(h_gemm<false, true, false>,
                         cudaFuncAttributeMaxDynamicSharedMemorySize, GEMM_SMEM);
    cudaFuncSetAttribute(h_gemm<true, false, true>,
                         cudaFuncAttributeMaxDynamicSharedMemorySize, GEMM_SMEM);
    cudaFuncSetAttribute(flash_kernel,
                         cudaFuncAttributeMaxDynamicSharedMemorySize, F_SMEM);

    // 0. weight transposes (fp16) + bias concat
    {
        dim3 blk(32, 8);
        prep_wT<<<dim3(DM / 32, DM / 32), blk>>>(Wq, wqkvT, DM, DM, 0);
        prep_wT<<<dim3(DM / 32, DM / 32), blk>>>(Wk, wqkvT, DM, DM, DM);
        prep_wT<<<dim3(DM / 32, DM / 32), blk>>>(Wv, wqkvT, DM, DM, 2 * DM);
        prep_wT<<<dim3(DM / 32, DM / 32), blk>>>(Wo, woT, DM, DM, 0);
        prep_wT<<<dim3(DF / 32, DM / 32), blk>>>(W1, w1T, DM, DF, 0);
        prep_wT<<<dim3(DM / 32, DF / 32), blk>>>(W2, w2T, DF, DM, 0);
        concat_b<<<12, 256>>>(bq, bk, bv, bcat);
    }

    // 1. LN1 -> n1 (fp16)
    ln_kernel<<<NTOK, 256>>>(x, alpha1, beta1, n1);

    // 2. fused QKV projection -> qkv (fp32)
    {
        dim3 grid(3 * DM / 128, NTOK / 128);
        h_gemm<false, false, false><<<grid, 256, GEMM_SMEM>>>(
            n1, wqkvT, bcat, nullptr, qkv, nullptr, DM, 3 * DM);
    }

    // 3-5. flash attention -> attn (fp16)
    {
        dim3 grid(SS / 128, HH, BB);
        flash_kernel<<<grid, 256, F_SMEM>>>(qkv, mask, attn);
    }

    // 6. h = x + attn @ Wo + bo  (fp32)
    {
        dim3 grid(DM / 128, NTOK / 128);
        h_gemm<false, true, false><<<grid, 256, GEMM_SMEM>>>(
            attn, woT, bo, x, h, nullptr, DM, DM);
    }

    // 7. LN2 -> n2 (fp16)
    ln_kernel<<<NTOK, 256>>>(h, alpha2, beta2, n2);

    // 8. ffn = relu(n2 @ W1 + b1)  (fp16)
    {
        dim3 grid(DF / 128, NTOK / 128);
        h_gemm<true, false, true><<<grid, 256, GEMM_SMEM>>>(
            n2, w1T, b1, nullptr, nullptr, ffn, DM, DF);
    }

    // 9. out = h + ffn @ W2 + b2  (fp32)
    {
        dim3 grid(DM / 128, NTOK / 128);
        h_gemm<false, true, false><<<grid, 256, GEMM_SMEM>>>(
            ffn, w2T, b2, h, out, nullptr, DF, DM);
    }
}

// round 16
// speedup vs baseline: 1.9708x; 1.2205x over previous
#include <cuda_runtime.h>
#include <cuda_fp16.h>
#include <math.h>
#include <stdint.h>

// Problem constants
#define BB 2
#define SS 2048
#define DM 1024
#define HH 16
#define HD 64
#define DF 4096
#define NTOK (BB * SS)          // 4096
#define NEGV (-1e9f)
#define EPS 1e-6f

// ---------------------------------------------------------------------------
// Scratch (device globals — no allocation allowed)
// ---------------------------------------------------------------------------
__device__ __half g_n1[NTOK * DM];                 // fp16 rows
__device__ __half g_qkv[(long)NTOK * 3 * DM];      // fp16 q|k|v rows
__device__ __half g_wqkvT[3 * DM * DM];            // [3072][1024] W^T fp16
__device__ __half g_woT[DM * DM];                  // [1024][1024]
__device__ __half g_w1T[(long)DF * DM];            // [4096][1024]
__device__ __half g_w2T[(long)DM * DF];            // [1024][4096]
__device__ float  g_bcat[3 * DM];
__device__ __half g_attn[NTOK * DM];               // fp16 rows
__device__ float  g_h[NTOK * DM];                  // raw fp32 (residual+LN2)
__device__ __half g_n2[NTOK * DM];                 // fp16 rows
__device__ __half g_ffn[(long)NTOK * DF];          // fp16 rows

// ---------------------------------------------------------------------------
// Helpers
// ---------------------------------------------------------------------------
__device__ __forceinline__ void mma_f16(float c[4], uint32_t a0, uint32_t a1,
                                        uint32_t a2, uint32_t a3,
                                        uint32_t b0, uint32_t b1) {
    asm volatile(
        "mma.sync.aligned.m16n8k16.row.col.f32.f16.f16.f32 "
        "{%0,%1,%2,%3}, {%4,%5,%6,%7}, {%8,%9}, {%0,%1,%2,%3};"
        : "+f"(c[0]), "+f"(c[1]), "+f"(c[2]), "+f"(c[3])
        : "r"(a0), "r"(a1), "r"(a2), "r"(a3), "r"(b0), "r"(b1));
}
__device__ __forceinline__ void ldm_x4_trans(uint32_t& d0, uint32_t& d1,
                                             uint32_t& d2, uint32_t& d3,
                                             uint32_t addr) {
    asm volatile(
        "ldmatrix.sync.aligned.m8n8.x4.trans.shared.b16 {%0,%1,%2,%3}, [%4];"
        : "=r"(d0), "=r"(d1), "=r"(d2), "=r"(d3) : "r"(addr));
}
__device__ __forceinline__ void cpa16(void* dst, const void* src) {
    uint32_t d = (uint32_t)__cvta_generic_to_shared(dst);
    asm volatile("cp.async.cg.shared.global [%0], [%1], 16;" :: "r"(d), "l"(src));
}
__device__ __forceinline__ void cpa_commit() {
    asm volatile("cp.async.commit_group;" ::: "memory");
}
__device__ __forceinline__ void cpa_wait0() {
    asm volatile("cp.async.wait_group 0;" ::: "memory");
}
__device__ __forceinline__ void cpa_wait1() {
    asm volatile("cp.async.wait_group 1;" ::: "memory");
}

// ---------------------------------------------------------------------------
// Weight transpose prep: out[(rowOff+n)*K + k] = fp16(W[k*N + n])
// ---------------------------------------------------------------------------
__global__ void prep_wT(const float* __restrict__ W, __half* __restrict__ out,
                        int K, int N, int rowOff) {
    __shared__ float t[32][33];
    int n0 = blockIdx.x * 32, k0 = blockIdx.y * 32;
    int tx = threadIdx.x, ty = threadIdx.y;
#pragma unroll
    for (int i = 0; i < 4; i++)
        t[ty + 8 * i][tx] = W[(long)(k0 + ty + 8 * i) * N + n0 + tx];
    __syncthreads();
#pragma unroll
    for (int i = 0; i < 4; i++)
        out[(long)(rowOff + n0 + ty + 8 * i) * K + k0 + tx] =
            __float2half_rn(t[tx][ty + 8 * i]);
}

__global__ __launch_bounds__(256) void concat_b(
    const float* __restrict__ bq, const float* __restrict__ bk,
    const float* __restrict__ bv, float* __restrict__ bcat) {
    int i = blockIdx.x * 256 + threadIdx.x;
    const float* b = (i < DM) ? bq : ((i < 2 * DM) ? bk : bv);
    bcat[i] = b[i & (DM - 1)];
}

// ---------------------------------------------------------------------------
// LayerNorm -> fp16 rows
// ---------------------------------------------------------------------------
__global__ __launch_bounds__(256) void ln_kernel(const float* __restrict__ x,
                                                 const float* __restrict__ alpha,
                                                 const float* __restrict__ beta,
                                                 __half* __restrict__ out) {
    long row = blockIdx.x;
    const float4* xr = (const float4*)(x + row * DM);
    float4 v = xr[threadIdx.x];

    float s  = v.x + v.y + v.z + v.w;
    float ss = v.x * v.x + v.y * v.y + v.z * v.z + v.w * v.w;

    __shared__ float sa[8], sb[8];
#pragma unroll
    for (int o = 16; o > 0; o >>= 1) {
        s  += __shfl_xor_sync(0xffffffffu, s, o);
        ss += __shfl_xor_sync(0xffffffffu, ss, o);
    }
    if ((threadIdx.x & 31) == 0) { sa[threadIdx.x >> 5] = s; sb[threadIdx.x >> 5] = ss; }
    __syncthreads();
    s = 0.f; ss = 0.f;
#pragma unroll
    for (int i = 0; i < 8; i++) { s += sa[i]; ss += sb[i]; }

    float mean = s * (1.0f / DM);
    float var  = (ss - (float)DM * mean * mean) * (1.0f / (DM - 1));
    var = fmaxf(var, 0.0f);
    float inv  = alpha[0] / (sqrtf(var) + EPS);
    float bta  = beta[0];

    __half2 h0 = __floats2half2_rn((v.x - mean) * inv + bta, (v.y - mean) * inv + bta);
    __half2 h1 = __floats2half2_rn((v.z - mean) * inv + bta, (v.w - mean) * inv + bta);
    __half2* orow = (__half2*)(out + row * DM) + 2 * threadIdx.x;
    orow[0] = h0;
    orow[1] = h1;
}

// ---------------------------------------------------------------------------
// Flash attention v4 — full fp16 MMA path.
// grid (S/128, H, B), 256 threads = 8 warps, 16 Q rows per warp.
// K/V half tiles [64 keys][72 halves], double-buffered via cp.async, consumed
// directly (no conversion pass).  1 __syncthreads per 64-key tile.
// S phase: m16n8k16, Q frags from gmem, K frags = adjacent-k half pairs (LDS.32).
// Scale 1/8 fused into the mask FMA (exact).
// PV phase: m16n8k16, P stored half2 per warp (stride 72 halves), V^T frags via
// ldmatrix.m8n8.x4.trans (row stride 144B -> conflict-free).
// ---------------------------------------------------------------------------
#define FH_KV 4608                     // halves per K or V stage
#define F_SMEM 55808                   // bytes: 2*KV + 2*KV + P(9216h) + 128 ints

__global__ __launch_bounds__(256, 2) void flash_kernel(
    const __half* __restrict__ qkv, const int* __restrict__ mask,
    __half* __restrict__ out) {
    constexpr int LDQ = 3 * DM;
    extern __shared__ __half hsm[];
    __half* Kst = hsm;                       // 2 x 4608 halves
    __half* Vst = hsm + 2 * FH_KV;           // 2 x 4608 halves
    __half* Pst = hsm + 4 * FH_KV;           // 8 warps x 1152 halves
    int* Mst = (int*)(hsm + 4 * FH_KV + 8 * 1152);   // 2 x 64 ints

    int qb = blockIdx.x * 128;
    int h  = blockIdx.y;
    int b  = blockIdx.z;
    const __half* qp = qkv + (long)b * SS * LDQ + h * HD;
    const __half* kp = qp + DM;
    const __half* vp = qp + 2 * DM;
    const int* mp = mask + b * SS;

    int tid = threadIdx.x, warp = tid >> 5, lane = tid & 31;
    int g = lane >> 2, tg = lane & 3;
    int rrow = qb + warp * 16 + g;
    const int lrow = tid >> 2;          // 0..63
    const int lcol = (tid & 3) * 16;    // half offset (two 16B chunks)

    // Q fragments straight from gmem (half pairs)
    uint32_t qf[4][4];
    {
        const __half* q0 = qp + (long)rrow * LDQ;
        const __half* q1 = qp + (long)(rrow + 8) * LDQ;
#pragma unroll
        for (int ks = 0; ks < 4; ks++) {
            qf[ks][0] = *(const uint32_t*)(q0 + 16 * ks + 2 * tg);
            qf[ks][1] = *(const uint32_t*)(q1 + 16 * ks + 2 * tg);
            qf[ks][2] = *(const uint32_t*)(q0 + 16 * ks + 8 + 2 * tg);
            qf[ks][3] = *(const uint32_t*)(q1 + 16 * ks + 8 + 2 * tg);
        }
    }

    uint32_t* Psu = (uint32_t*)(Pst + warp * 1152);
    uint32_t vbase = (uint32_t)__cvta_generic_to_shared(Vst);
    const uint32_t vtoff = ((((lane >> 3) & 1) * 8 + (lane & 7)) * 72 +
                            (lane >> 4) * 8) * 2;

    float m0 = -INFINITY, m1 = -INFINITY, l0 = 0.f, l1 = 0.f;
    float oacc[8][4];
#pragma unroll
    for (int nf = 0; nf < 8; nf++)
#pragma unroll
        for (int c = 0; c < 4; c++) oacc[nf][c] = 0.f;

    auto issue = [&](int t, int s) {
        int k0 = t * 64;
        const __half* kg = kp + (long)(k0 + lrow) * LDQ + lcol;
        const __half* vg = vp + (long)(k0 + lrow) * LDQ + lcol;
        __half* kw = Kst + s * FH_KV + lrow * 72 + lcol;
        __half* vw = Vst + s * FH_KV + lrow * 72 + lcol;
        cpa16(kw, kg);
        cpa16(kw + 8, kg + 8);
        cpa16(vw, vg);
        cpa16(vw + 8, vg + 8);
        if (tid < 16) cpa16(&Mst[s * 64 + tid * 4], &mp[k0 + tid * 4]);
        cpa_commit();
    };

    issue(0, 0);

    const int nT = SS / 64;
    for (int t = 0; t < nT; t++) {
        int s = t & 1;
        cpa_wait0();
        __syncthreads();   // tile t visible; all warps done with stage s^1

        if (t + 1 < nT) issue(t + 1, s ^ 1);

        const uint32_t* Ku = (const uint32_t*)(Kst + s * FH_KV);
        uint32_t vb = vbase + s * FH_KV * 2;
        const int* Ms = Mst + s * 64;

        // S = Q @ K^T (fp16, fp32 accum); 16x64 per warp
        float sacc[8][4];
#pragma unroll
        for (int nf = 0; nf < 8; nf++)
#pragma unroll
            for (int c = 0; c < 4; c++) sacc[nf][c] = 0.f;
#pragma unroll
        for (int ks = 0; ks < 4; ks++) {
#pragma unroll
            for (int nf = 0; nf < 8; nf++) {
                uint32_t b0 = Ku[(nf * 8 + g) * 36 + ks * 8 + tg];
                uint32_t b1 = Ku[(nf * 8 + g) * 36 + ks * 8 + tg + 4];
                mma_f16(sacc[nf], qf[ks][0], qf[ks][1], qf[ks][2], qf[ks][3],
                        b0, b1);
            }
        }

        // scale 1/8 + mask + tile rowmax
        float tm0 = -INFINITY, tm1 = -INFINITY;
#pragma unroll
        for (int nf = 0; nf < 8; nf++) {
            int2 mm = *(const int2*)&Ms[nf * 8 + 2 * tg];
            float fx = (mm.x == 0) ? NEGV : 0.f;
            float fy = (mm.y == 0) ? NEGV : 0.f;
            sacc[nf][0] = sacc[nf][0] * 0.125f + fx;
            sacc[nf][1] = sacc[nf][1] * 0.125f + fy;
            sacc[nf][2] = sacc[nf][2] * 0.125f + fx;
            sacc[nf][3] = sacc[nf][3] * 0.125f + fy;
            tm0 = fmaxf(tm0, fmaxf(sacc[nf][0], sacc[nf][1]));
            tm1 = fmaxf(tm1, fmaxf(sacc[nf][2], sacc[nf][3]));
        }
#pragma unroll
        for (int o = 1; o <= 2; o <<= 1) {
            tm0 = fmaxf(tm0, __shfl_xor_sync(0xffffffffu, tm0, o));
            tm1 = fmaxf(tm1, __shfl_xor_sync(0xffffffffu, tm1, o));
        }
        float nm0 = fmaxf(m0, tm0), nm1 = fmaxf(m1, tm1);
        float r0 = __expf(m0 - nm0), r1 = __expf(m1 - nm1);

        float s0 = 0.f, s1 = 0.f;
#pragma unroll
        for (int nf = 0; nf < 8; nf++) {
            sacc[nf][0] = __expf(sacc[nf][0] - nm0);
            sacc[nf][1] = __expf(sacc[nf][1] - nm0);
            sacc[nf][2] = __expf(sacc[nf][2] - nm1);
            sacc[nf][3] = __expf(sacc[nf][3] - nm1);
            s0 += sacc[nf][0] + sacc[nf][1];
            s1 += sacc[nf][2] + sacc[nf][3];
        }
#pragma unroll
        for (int o = 1; o <= 2; o <<= 1) {
            s0 += __shfl_xor_sync(0xffffffffu, s0, o);
            s1 += __shfl_xor_sync(0xffffffffu, s1, o);
        }
        l0 = l0 * r0 + s0; l1 = l1 * r1 + s1;
        m0 = nm0; m1 = nm1;
#pragma unroll
        for (int nf = 0; nf < 8; nf++) {
            oacc[nf][0] *= r0; oacc[nf][1] *= r0;
            oacc[nf][2] *= r1; oacc[nf][3] *= r1;
        }

        // P -> smem as half2 (warp-private, 16 x 72-half rows)
#pragma unroll
        for (int nf = 0; nf < 8; nf++) {
            __half2 p0 = __floats2half2_rn(sacc[nf][0], sacc[nf][1]);
            __half2 p1 = __floats2half2_rn(sacc[nf][2], sacc[nf][3]);
            Psu[g * 36 + nf * 4 + tg] = *(uint32_t*)&p0;
            Psu[(g + 8) * 36 + nf * 4 + tg] = *(uint32_t*)&p1;
        }
        __syncwarp();

        // O += P @ V (fp16); V^T frags via ldmatrix.trans
#pragma unroll
        for (int ks = 0; ks < 4; ks++) {
            uint32_t a0 = Psu[g * 36 + ks * 8 + tg];
            uint32_t a1 = Psu[(g + 8) * 36 + ks * 8 + tg];
            uint32_t a2 = Psu[g * 36 + ks * 8 + tg + 4];
            uint32_t a3 = Psu[(g + 8) * 36 + ks * 8 + tg + 4];
#pragma unroll
            for (int nfp = 0; nfp < 4; nfp++) {
                uint32_t d0, d1, d2, d3;
                ldm_x4_trans(d0, d1, d2, d3, vb + ks * 2304 + nfp * 32 + vtoff);
                mma_f16(oacc[2 * nfp], a0, a1, a2, a3, d0, d1);
                mma_f16(oacc[2 * nfp + 1], a0, a1, a2, a3, d2, d3);
            }
        }
    }

    // epilogue: fp16 attn
    float i0 = 1.f / l0, i1 = 1.f / l1;
    __half* op = out + (long)b * SS * DM + h * HD;
#pragma unroll
    for (int nf = 0; nf < 8; nf++) {
        int c = nf * 8 + 2 * tg;
        *(__half2*)(op + (long)rrow * DM + c) =
            __floats2half2_rn(oacc[nf][0] * i0, oacc[nf][1] * i0);
        *(__half2*)(op + (long)(rrow + 8) * DM + c) =
            __floats2half2_rn(oacc[nf][2] * i1, oacc[nf][3] * i1);
    }
}

// ---------------------------------------------------------------------------
// fp16 GEMM v5 (R14, unchanged): 3-stage cp.async ring.
// ---------------------------------------------------------------------------
#define H_AS 40
#define H_STG (128 * H_AS)
#define GEMM_SMEM (3 * 2 * H_STG * 2)              // 61,440 B

template <bool RELU, bool RES, bool OUTH>
__global__ __launch_bounds__(256, 2) void h_gemm(
    const __half* __restrict__ A, const __half* __restrict__ Bt,
    const float* __restrict__ bias, const float* __restrict__ res,
    float* __restrict__ C, __half* __restrict__ Ch, int K, int ldc) {
    extern __shared__ __half hsm2[];
    __half* Ast = hsm2;
    __half* Bst = hsm2 + 3 * H_STG;

    int bm = blockIdx.y * 128;
    int bn = blockIdx.x * 128;
    int tid = threadIdx.x, warp = tid >> 5, lane = tid & 31;
    int g = lane >> 2, tg = lane & 3;
    int wm = warp >> 2, wn = warp & 3;

    const int ar = tid >> 1;
    const int ac = (tid & 1) * 16;
    const int nT = K / 32;

    auto issue = [&](int t, int s) {
        const __half* Ag = A + (long)(bm + ar) * K + t * 32 + ac;
        const __half* Bg = Bt + (long)(bn + ar) * K + t * 32 + ac;
        __half* Aw = Ast + s * H_STG + ar * H_AS + ac;
        __half* Bw = Bst + s * H_STG + ar * H_AS + ac;
        cpa16(Aw, Ag);
        cpa16(Aw + 8, Ag + 8);
        cpa16(Bw, Bg);
        cpa16(Bw + 8, Bg + 8);
        cpa_commit();
    };

    issue(0, 0);
    issue(1, 1);

    float acc[4][4][4];
#pragma unroll
    for (int i = 0; i < 4; i++)
#pragma unroll
        for (int j = 0; j < 4; j++)
#pragma unroll
            for (int c = 0; c < 4; c++) acc[i][j][c] = 0.f;

    for (int t = 0; t < nT; t++) {
        cpa_wait1();
        __syncthreads();

        if (t + 2 < nT) issue(t + 2, (t + 2) % 3);
        else cpa_commit();

        const uint32_t* As = (const uint32_t*)(Ast + (t % 3) * H_STG);
        const uint32_t* Bs = (const uint32_t*)(Bst + (t % 3) * H_STG);

#pragma unroll
        for (int ks = 0; ks < 2; ks++) {
            uint32_t af[4][4];
            uint32_t bf[4][2];
#pragma unroll
            for (int mt = 0; mt < 4; mt++) {
                int r = wm * 64 + mt * 16 + g;
                af[mt][0] = As[r * 20 + ks * 8 + tg];
                af[mt][1] = As[(r + 8) * 20 + ks * 8 + tg];
                af[mt][2] = As[r * 20 + ks * 8 + 4 + tg];
                af[mt][3] = As[(r + 8) * 20 + ks * 8 + 4 + tg];
            }
#pragma unroll
            for (int nt = 0; nt < 4; nt++) {
                int c = wn * 32 + nt * 8 + g;
                bf[nt][0] = Bs[c * 20 + ks * 8 + tg];
                bf[nt][1] = Bs[c * 20 + ks * 8 + 4 + tg];
            }
#pragma unroll
            for (int mt = 0; mt < 4; mt++)
#pragma unroll
                for (int nt = 0; nt < 4; nt++)
                    mma_f16(acc[mt][nt], af[mt][0], af[mt][1], af[mt][2],
                            af[mt][3], bf[nt][0], bf[nt][1]);
        }
    }

#pragma unroll
    for (int mt = 0; mt < 4; mt++) {
        int r = bm + wm * 64 + mt * 16 + g;
#pragma unroll
        for (int nt = 0; nt < 4; nt++) {
            int c = bn + wn * 32 + nt * 8 + tg * 2;
            float v0 = acc[mt][nt][0], v1 = acc[mt][nt][1];
            float v2 = acc[mt][nt][2], v3 = acc[mt][nt][3];
            {
                float2 bv = *(const float2*)(bias + c);
                v0 += bv.x; v1 += bv.y; v2 += bv.x; v3 += bv.y;
            }
            if (RELU) {
                v0 = fmaxf(v0, 0.f); v1 = fmaxf(v1, 0.f);
                v2 = fmaxf(v2, 0.f); v3 = fmaxf(v3, 0.f);
            }
            if (RES) {
                float2 r0 = *(const float2*)(res + (long)r * ldc + c);
                float2 r1 = *(const float2*)(res + (long)(r + 8) * ldc + c);
                v0 += r0.x; v1 += r0.y; v2 += r1.x; v3 += r1.y;
            }
            if (OUTH) {
                *(__half2*)(Ch + (long)r * ldc + c) = __floats2half2_rn(v0, v1);
                *(__half2*)(Ch + (long)(r + 8) * ldc + c) = __floats2half2_rn(v2, v3);
            } else {
                *(float2*)(C + (long)r * ldc + c) = make_float2(v0, v1);
                *(float2*)(C + (long)(r + 8) * ldc + c) = make_float2(v2, v3);
            }
        }
    }
}

// ---------------------------------------------------------------------------
// Host side
// ---------------------------------------------------------------------------
template <typename T>
static void* symv(const T& s) {
    void* p = nullptr;
    cudaGetSymbolAddress(&p, s);
    return p;
}

extern "C" void kernel_launch(void* const* d_in, const int* in_sizes, int n_in,
                              void* d_out, int out_size) {
    const float* x      = (const float*)d_in[0];
    const int*   mask   = (const int*)d_in[1];
    const float* Wq     = (const float*)d_in[2];
    const float* bq     = (const float*)d_in[3];
    const float* Wk     = (const float*)d_in[4];
    const float* bk     = (const float*)d_in[5];
    const float* Wv     = (const float*)d_in[6];
    const float* bv     = (const float*)d_in[7];
    const float* Wo     = (const float*)d_in[8];
    const float* bo     = (const float*)d_in[9];
    const float* W1     = (const float*)d_in[10];
    const float* b1     = (const float*)d_in[11];
    const float* W2     = (const float*)d_in[12];
    const float* b2     = (const float*)d_in[13];
    const float* alpha1 = (const float*)d_in[14];
    const float* beta1  = (const float*)d_in[15];
    const float* alpha2 = (const float*)d_in[16];
    const float* beta2  = (const float*)d_in[17];
    float* out = (float*)d_out;

    __half* n1    = (__half*)symv(g_n1);
    __half* qkv   = (__half*)symv(g_qkv);
    __half* wqkvT = (__half*)symv(g_wqkvT);
    __half* woT   = (__half*)symv(g_woT);
    __half* w1T   = (__half*)symv(g_w1T);
    __half* w2T   = (__half*)symv(g_w2T);
    float*  bcat  = (float*)symv(g_bcat);
    __half* attn  = (__half*)symv(g_attn);
    float*  h     = (float*)symv(g_h);
    __half* n2    = (__half*)symv(g_n2);
    __half* ffn   = (__half*)symv(g_ffn);

    cudaFuncSetAttribute(h_gemm<false, false, true>,
                         cudaFuncAttributeMaxDynamicSharedMemorySize, GEMM_SMEM);
    cudaFuncSetAttribute(h_gemm<false, true, false>,
                         cudaFuncAttributeMaxDynamicSharedMemorySize, GEMM_SMEM);
    cudaFuncSetAttribute(h_gemm<true, false, true>,
                         cudaFuncAttributeMaxDynamicSharedMemorySize, GEMM_SMEM);
    cudaFuncSetAttribute(flash_kernel,
                         cudaFuncAttributeMaxDynamicSharedMemorySize, F_SMEM);

    // 0. weight transposes (fp16) + bias concat
    {
        dim3 blk(32, 8);
        prep_wT<<<dim3(DM / 32, DM / 32), blk>>>(Wq, wqkvT, DM, DM, 0);
        prep_wT<<<dim3(DM / 32, DM / 32), blk>>>(Wk, wqkvT, DM, DM, DM);
        prep_wT<<<dim3(DM / 32, DM / 32), blk>>>(Wv, wqkvT, DM, DM, 2 * DM);
        prep_wT<<<dim3(DM / 32, DM / 32), blk>>>(Wo, woT, DM, DM, 0);
        prep_wT<<<dim3(DF / 32, DM / 32), blk>>>(W1, w1T, DM, DF, 0);
        prep_wT<<<dim3(DM / 32, DF / 32), blk>>>(W2, w2T, DF, DM, 0);
        concat_b<<<12, 256>>>(bq, bk, bv, bcat);
    }

    // 1. LN1 -> n1 (fp16)
    ln_kernel<<<NTOK, 256>>>(x, alpha1, beta1, n1);

    // 2. fused QKV projection -> qkv (fp16)
    {
        dim3 grid(3 * DM / 128, NTOK / 128);
        h_gemm<false, false, true><<<grid, 256, GEMM_SMEM>>>(
            n1, wqkvT, bcat, nullptr, nullptr, qkv, DM, 3 * DM);
    }

    // 3-5. flash attention -> attn (fp16)
    {
        dim3 grid(SS / 128, HH, BB);
        flash_kernel<<<grid, 256, F_SMEM>>>(qkv, mask, attn);
    }

    // 6. h = x + attn @ Wo + bo  (fp32)
    {
        dim3 grid(DM / 128, NTOK / 128);
        h_gemm<false, true, false><<<grid, 256, GEMM_SMEM>>>(
            attn, woT, bo, x, h, nullptr, DM, DM);
    }

    // 7. LN2 -> n2 (fp16)
    ln_kernel<<<NTOK, 256>>>(h, alpha2, beta2, n2);

    // 8. ffn = relu(n2 @ W1 + b1)  (fp16)
    {
        dim3 grid(DF / 128, NTOK / 128);
        h_gemm<true, false, true><<<grid, 256, GEMM_SMEM>>>(
            n2, w1T, b1, nullptr, nullptr, ffn, DM, DF);
    }

    // 9. out = h + ffn @ W2 + b2  (fp32)
    {
        dim3 grid(DM / 128, NTOK / 128);
        h_gemm<false, true, false><<<grid, 256, GEMM_SMEM>>>(
            ffn, w2T, b2, h, out, nullptr, DF, DM);
    }
}